// round 1
// baseline (speedup 1.0000x reference)
#include <cuda_runtime.h>
#include <math.h>

#define Bb 4
#define Ss 2048
#define Ee 1024
#define Hh 16
#define Dk 64
#define Mm (Bb*Ss)   /* 8192 */

// scratch (allocation-free rule: __device__ globals)
__device__ float g_q[Bb*Ss*Ee];
__device__ float g_k[Bb*Ss*Ee];
__device__ float g_v[Bb*Ss*Ee];
__device__ float g_ctx[Bb*Ss*Ee];

// ---------------------------------------------------------------------------
// Tiled GEMM: C[M,N] = A[M,K] @ W[N,K]^T, optional epilogue cos(val + theta[n%64])
// 64x64 tile, BK=16, 256 threads, 4x4 per-thread register tile.
// ---------------------------------------------------------------------------
template<bool DO_COS>
__global__ __launch_bounds__(256) void gemm64(const float* __restrict__ A,
                                              const float* __restrict__ W,
                                              const float* __restrict__ theta,
                                              float* __restrict__ C,
                                              int M, int N, int K)
{
    const int BK = 16, PA = 68;
    __shared__ float As[BK * PA];   // transposed: As[k][m]
    __shared__ float Bs[BK * PA];   // transposed: Bs[k][n]

    int tid = threadIdx.x;
    int txi = tid & 15, tyi = tid >> 4;
    int m0 = blockIdx.y * 64, n0 = blockIdx.x * 64;

    int lr = tid >> 2;            // 0..63 tile row
    int lc = (tid & 3) << 2;      // 0,4,8,12 within BK
    const float* Ap = A + (size_t)(m0 + lr) * K + lc;
    const float* Wp = W + (size_t)(n0 + lr) * K + lc;

    float acc[4][4] = {};

    for (int k0 = 0; k0 < K; k0 += BK) {
        float4 a = *(const float4*)(Ap + k0);
        float4 b = *(const float4*)(Wp + k0);
        As[(lc+0)*PA + lr] = a.x; As[(lc+1)*PA + lr] = a.y;
        As[(lc+2)*PA + lr] = a.z; As[(lc+3)*PA + lr] = a.w;
        Bs[(lc+0)*PA + lr] = b.x; Bs[(lc+1)*PA + lr] = b.y;
        Bs[(lc+2)*PA + lr] = b.z; Bs[(lc+3)*PA + lr] = b.w;
        __syncthreads();
#pragma unroll
        for (int kk = 0; kk < BK; kk++) {
            float4 a4 = *(const float4*)(&As[kk*PA + (tyi << 2)]);
            float4 b4 = *(const float4*)(&Bs[kk*PA + (txi << 2)]);
            float av[4] = {a4.x, a4.y, a4.z, a4.w};
            float bv[4] = {b4.x, b4.y, b4.z, b4.w};
#pragma unroll
            for (int i = 0; i < 4; i++)
#pragma unroll
                for (int j = 0; j < 4; j++)
                    acc[i][j] = fmaf(av[i], bv[j], acc[i][j]);
        }
        __syncthreads();
    }

#pragma unroll
    for (int i = 0; i < 4; i++) {
        int m = m0 + (tyi << 2) + i;
        float4 ov;
        float* dst = C + (size_t)m * N + n0 + (txi << 2);
        int nb = n0 + (txi << 2);
        float r[4];
#pragma unroll
        for (int j = 0; j < 4; j++) {
            float v = acc[i][j];
            if (DO_COS) v = cosf(v + theta[(nb + j) & (Dk - 1)]);
            r[j] = v;
        }
        ov.x = r[0]; ov.y = r[1]; ov.z = r[2]; ov.w = r[3];
        *(float4*)dst = ov;
    }
}

// ---------------------------------------------------------------------------
// Flash attention: per (b,h), 64-query tile per block, loop over 64-KV tiles.
// 256 threads; 4x4 register tiles for QK^T and PV; online softmax.
// q,k,v,ctx all in [B,S,E] layout (head h occupies cols h*64..h*64+63).
// ---------------------------------------------------------------------------
#define APITCH 68
#define PPITCH 65
#define ATT_SMEM ((3*64*APITCH + 64*PPITCH + 3*64) * 4)

__global__ __launch_bounds__(256) void attn64(const float* __restrict__ q,
                                              const float* __restrict__ k,
                                              const float* __restrict__ v,
                                              float* __restrict__ ctx)
{
    extern __shared__ float sm[];
    float* Qt = sm;                      // Qt[d*APITCH + r]
    float* Kt = Qt + 64 * APITCH;        // Kt[d*APITCH + j]
    float* Vs = Kt + 64 * APITCH;        // Vs[j*APITCH + d]
    float* Ps = Vs + 64 * APITCH;        // Ps[r*PPITCH + c]
    float* mrow = Ps + 64 * PPITCH;
    float* lrow = mrow + 64;
    float* srow = lrow + 64;

    int tid = threadIdx.x;
    int txi = tid & 15, tyi = tid >> 4;
    int bh = blockIdx.y;
    int b = bh >> 4, h = bh & 15;
    int q0 = blockIdx.x * 64;
    size_t base = (size_t)b * Ss * Ee + (size_t)h * Dk;
    const float* qb = q + base;
    const float* kb = k + base;
    const float* vb = v + base;

    int lr = tid >> 2;             // 0..63
    int lc = (tid & 3) << 4;       // 0,16,32,48

    // Load Q tile transposed (once)
    {
        const float* src = qb + (size_t)(q0 + lr) * Ee + lc;
#pragma unroll
        for (int u = 0; u < 4; u++) {
            float4 a = *(const float4*)(src + u * 4);
            int d = lc + u * 4;
            Qt[(d+0)*APITCH + lr] = a.x; Qt[(d+1)*APITCH + lr] = a.y;
            Qt[(d+2)*APITCH + lr] = a.z; Qt[(d+3)*APITCH + lr] = a.w;
        }
    }
    if (tid < 64) { mrow[tid] = -1e30f; lrow[tid] = 0.0f; }
    float o[4][4] = {};
    __syncthreads();

    for (int j0 = 0; j0 < Ss; j0 += 64) {
        // Load K transposed + V natural
        {
            const float* ksrc = kb + (size_t)(j0 + lr) * Ee + lc;
            const float* vsrc = vb + (size_t)(j0 + lr) * Ee + lc;
#pragma unroll
            for (int u = 0; u < 4; u++) {
                float4 a = *(const float4*)(ksrc + u * 4);
                int d = lc + u * 4;
                Kt[(d+0)*APITCH + lr] = a.x; Kt[(d+1)*APITCH + lr] = a.y;
                Kt[(d+2)*APITCH + lr] = a.z; Kt[(d+3)*APITCH + lr] = a.w;
                float4 vv = *(const float4*)(vsrc + u * 4);
                *(float4*)(&Vs[lr*APITCH + d]) = vv;
            }
        }
        __syncthreads();

        // GEMM1: S = Q @ K^T * 1/sqrt(64)
        float s[4][4] = {};
#pragma unroll
        for (int d = 0; d < 64; d++) {
            float4 a4 = *(const float4*)(&Qt[d*APITCH + (tyi << 2)]);
            float4 b4 = *(const float4*)(&Kt[d*APITCH + (txi << 2)]);
            float av[4] = {a4.x, a4.y, a4.z, a4.w};
            float bv[4] = {b4.x, b4.y, b4.z, b4.w};
#pragma unroll
            for (int i = 0; i < 4; i++)
#pragma unroll
                for (int j = 0; j < 4; j++)
                    s[i][j] = fmaf(av[i], bv[j], s[i][j]);
        }
#pragma unroll
        for (int i = 0; i < 4; i++)
#pragma unroll
            for (int j = 0; j < 4; j++)
                Ps[((tyi<<2)+i)*PPITCH + (txi<<2)+j] = s[i][j] * 0.125f;
        __syncthreads();

        // Online softmax: 4 threads per row
        {
            int r = tid >> 2;
            float* row = Ps + r * PPITCH + (tid & 3) * 16;
            float mx = -1e30f;
#pragma unroll
            for (int c = 0; c < 16; c++) mx = fmaxf(mx, row[c]);
            mx = fmaxf(mx, __shfl_xor_sync(0xffffffffu, mx, 1));
            mx = fmaxf(mx, __shfl_xor_sync(0xffffffffu, mx, 2));
            float mold = mrow[r];
            float mnew = fmaxf(mold, mx);
            float sum = 0.0f;
#pragma unroll
            for (int c = 0; c < 16; c++) {
                float p = __expf(row[c] - mnew);
                row[c] = p;
                sum += p;
            }
            sum += __shfl_xor_sync(0xffffffffu, sum, 1);
            sum += __shfl_xor_sync(0xffffffffu, sum, 2);
            if ((tid & 3) == 0) {
                float sc = __expf(mold - mnew);
                srow[r] = sc;
                lrow[r] = lrow[r] * sc + sum;
                mrow[r] = mnew;
            }
        }
        __syncthreads();

        // Rescale accumulator, then GEMM2: O += P @ V
#pragma unroll
        for (int i = 0; i < 4; i++) {
            float sc = srow[(tyi << 2) + i];
#pragma unroll
            for (int j = 0; j < 4; j++) o[i][j] *= sc;
        }
#pragma unroll
        for (int j = 0; j < 64; j++) {
            float4 v4 = *(const float4*)(&Vs[j*APITCH + (txi << 2)]);
            float vv[4] = {v4.x, v4.y, v4.z, v4.w};
            float p[4];
#pragma unroll
            for (int i = 0; i < 4; i++) p[i] = Ps[((tyi<<2)+i)*PPITCH + j];
#pragma unroll
            for (int i = 0; i < 4; i++)
#pragma unroll
                for (int jj = 0; jj < 4; jj++)
                    o[i][jj] = fmaf(p[i], vv[jj], o[i][jj]);
        }
        __syncthreads();
    }

    // Normalize and write ctx[b, s, h*64 + d]
#pragma unroll
    for (int i = 0; i < 4; i++) {
        int r = (tyi << 2) + i;
        float inv = 1.0f / lrow[r];
        float* dst = ctx + (size_t)b * Ss * Ee + (size_t)(q0 + r) * Ee
                   + h * Dk + (txi << 2);
        float4 ov;
        ov.x = o[i][0] * inv; ov.y = o[i][1] * inv;
        ov.z = o[i][2] * inv; ov.w = o[i][3] * inv;
        *(float4*)dst = ov;
    }
}

// ---------------------------------------------------------------------------
extern "C" void kernel_launch(void* const* d_in, const int* in_sizes, int n_in,
                              void* d_out, int out_size)
{
    const float* x     = (const float*)d_in[0];
    const float* Wq    = (const float*)d_in[1];
    const float* Wk    = (const float*)d_in[2];
    const float* Wv    = (const float*)d_in[3];
    const float* Wo    = (const float*)d_in[4];
    const float* theta = (const float*)d_in[5];
    float* out = (float*)d_out;

    float *qp, *kp, *vp, *ctxp;
    cudaGetSymbolAddress((void**)&qp, g_q);
    cudaGetSymbolAddress((void**)&kp, g_k);
    cudaGetSymbolAddress((void**)&vp, g_v);
    cudaGetSymbolAddress((void**)&ctxp, g_ctx);

    dim3 blk(256);
    dim3 g1(Ee / 64, Mm / 64);           // (16, 128)
    gemm64<true><<<g1, blk>>>(x, Wq, theta, qp, Mm, Ee, Ee);
    gemm64<true><<<g1, blk>>>(x, Wk, theta, kp, Mm, Ee, Ee);
    gemm64<true><<<g1, blk>>>(x, Wv, theta, vp, Mm, Ee, Ee);

    cudaFuncSetAttribute(attn64, cudaFuncAttributeMaxDynamicSharedMemorySize,
                         ATT_SMEM);
    dim3 g2(Ss / 64, Bb * Hh);           // (32, 64)
    attn64<<<g2, blk, ATT_SMEM>>>(qp, kp, vp, ctxp);

    gemm64<false><<<g1, blk>>>(ctxp, Wo, nullptr, out, Mm, Ee, Ee);
}

// round 3
// speedup vs baseline: 1.3036x; 1.3036x over previous
#include <cuda_runtime.h>
#include <cuda_bf16.h>
#include <math.h>
#include <stdint.h>

#define Bb 4
#define Ss 2048
#define Ee 1024
#define Hh 16
#define Dk 64
#define Mm (Bb*Ss)   /* 8192 */

// ------------------------- device scratch (no allocs) ----------------------
__device__ float g_q[Mm*Ee];
__device__ float g_k[Mm*Ee];
__device__ float g_v[Mm*Ee];
__device__ __nv_bfloat16 g_xhi[Mm*Ee];
__device__ __nv_bfloat16 g_xlo[Mm*Ee];
__device__ __nv_bfloat16 g_chi[Mm*Ee];   // ctx hi
__device__ __nv_bfloat16 g_clo[Mm*Ee];   // ctx lo
__device__ __nv_bfloat16 g_whi[4*Ee*Ee]; // Wq,Wk,Wv,Wo hi
__device__ __nv_bfloat16 g_wlo[4*Ee*Ee]; // Wq,Wk,Wv,Wo lo

// ------------------------- warp HMMA m16n8k16 bf16 --------------------------
__device__ __forceinline__ void mma16816(float* d, const uint32_t* a,
                                         const uint32_t* b)
{
    asm volatile(
        "mma.sync.aligned.m16n8k16.row.col.f32.bf16.bf16.f32 "
        "{%0,%1,%2,%3}, {%4,%5,%6,%7}, {%8,%9}, {%0,%1,%2,%3};"
        : "+f"(d[0]), "+f"(d[1]), "+f"(d[2]), "+f"(d[3])
        : "r"(a[0]), "r"(a[1]), "r"(a[2]), "r"(a[3]), "r"(b[0]), "r"(b[1]));
}

// ------------------------- fp32 -> bf16 hi/lo split -------------------------
__global__ __launch_bounds__(256) void split_kernel(const float4* __restrict__ src,
                                                    __nv_bfloat16* __restrict__ hi,
                                                    __nv_bfloat16* __restrict__ lo,
                                                    int n4)
{
    int i = blockIdx.x * 256 + threadIdx.x;
    if (i >= n4) return;
    float4 v = src[i];
    float vv[4] = {v.x, v.y, v.z, v.w};
    __nv_bfloat16 h[4], l[4];
#pragma unroll
    for (int j = 0; j < 4; j++) {
        h[j] = __float2bfloat16(vv[j]);
        l[j] = __float2bfloat16(vv[j] - __bfloat162float(h[j]));
    }
    __nv_bfloat162* hp = (__nv_bfloat162*)(hi + (size_t)i * 4);
    __nv_bfloat162* lp = (__nv_bfloat162*)(lo + (size_t)i * 4);
    hp[0] = __nv_bfloat162{h[0], h[1]}; hp[1] = __nv_bfloat162{h[2], h[3]};
    lp[0] = __nv_bfloat162{l[0], l[1]}; lp[1] = __nv_bfloat162{l[2], l[3]};
}

// ------------------------- HMMA split-bf16 GEMM ------------------------------
// C[M,1024] = A[M,1024] @ W[1024,1024]^T  (A,W as bf16 hi/lo pairs)
// 128x128 CTA tile, 8 warps (warp tile 64x32), K-chunk 64 (4 k16 steps),
// 3 split MMAs per step. DO_COS: C = cos(acc + theta[n & 63]).
#define PCH 72
#define GEMM_SMEM (4 * 128 * PCH * 2)   /* 73728 B */

template<bool DO_COS>
__global__ __launch_bounds__(256) void hmma_gemm(
    const __nv_bfloat16* __restrict__ Ahi, const __nv_bfloat16* __restrict__ Alo,
    const __nv_bfloat16* __restrict__ Whi, const __nv_bfloat16* __restrict__ Wlo,
    const float* __restrict__ theta, float* __restrict__ C)
{
    extern __shared__ __align__(16) char smem[];
    __nv_bfloat16* sAh = (__nv_bfloat16*)smem;
    __nv_bfloat16* sAl = sAh + 128 * PCH;
    __nv_bfloat16* sWh = sAl + 128 * PCH;
    __nv_bfloat16* sWl = sWh + 128 * PCH;

    int tid = threadIdx.x, wid = tid >> 5, lane = tid & 31;
    int wm = wid & 1, wn = wid >> 1;          // warp tile: rows wm*64, cols wn*32
    int g = lane >> 2, t = lane & 3;
    int m0 = blockIdx.y * 128, n0 = blockIdx.x * 128;

    int lrow = tid >> 1;                      // 0..127
    int lseg = (tid & 1) * 32;                // 0 or 32 (bf16 elems)

    float acc[4][4][4] = {};                  // [mf][nf][reg]

    for (int c = 0; c < 16; c++) {
        __syncthreads();
        {
            size_t gA = (size_t)(m0 + lrow) * Ee + c * 64 + lseg;
            size_t gW = (size_t)(n0 + lrow) * Ee + c * 64 + lseg;
            uint32_t so = lrow * PCH + lseg;
#pragma unroll
            for (int u = 0; u < 4; u++) {
                *(uint4*)(sAh + so + u * 8) = *(const uint4*)(Ahi + gA + u * 8);
                *(uint4*)(sAl + so + u * 8) = *(const uint4*)(Alo + gA + u * 8);
                *(uint4*)(sWh + so + u * 8) = *(const uint4*)(Whi + gW + u * 8);
                *(uint4*)(sWl + so + u * 8) = *(const uint4*)(Wlo + gW + u * 8);
            }
        }
        __syncthreads();

#pragma unroll
        for (int ks = 0; ks < 4; ks++) {
            int cc = ks * 16 + 2 * t;
            uint32_t ah[4][4], al[4][4];
#pragma unroll
            for (int mf = 0; mf < 4; mf++) {
                int r = wm * 64 + mf * 16 + g;
                ah[mf][0] = *(const uint32_t*)&sAh[r * PCH + cc];
                ah[mf][1] = *(const uint32_t*)&sAh[(r + 8) * PCH + cc];
                ah[mf][2] = *(const uint32_t*)&sAh[r * PCH + cc + 8];
                ah[mf][3] = *(const uint32_t*)&sAh[(r + 8) * PCH + cc + 8];
                al[mf][0] = *(const uint32_t*)&sAl[r * PCH + cc];
                al[mf][1] = *(const uint32_t*)&sAl[(r + 8) * PCH + cc];
                al[mf][2] = *(const uint32_t*)&sAl[r * PCH + cc + 8];
                al[mf][3] = *(const uint32_t*)&sAl[(r + 8) * PCH + cc + 8];
            }
            uint32_t bh[4][2], bl[4][2];
#pragma unroll
            for (int nf = 0; nf < 4; nf++) {
                int r = wn * 32 + nf * 8 + g;
                bh[nf][0] = *(const uint32_t*)&sWh[r * PCH + cc];
                bh[nf][1] = *(const uint32_t*)&sWh[r * PCH + cc + 8];
                bl[nf][0] = *(const uint32_t*)&sWl[r * PCH + cc];
                bl[nf][1] = *(const uint32_t*)&sWl[r * PCH + cc + 8];
            }
#pragma unroll
            for (int mf = 0; mf < 4; mf++)
#pragma unroll
                for (int nf = 0; nf < 4; nf++) {
                    mma16816(acc[mf][nf], ah[mf], bh[nf]);
                    mma16816(acc[mf][nf], ah[mf], bl[nf]);
                    mma16816(acc[mf][nf], al[mf], bh[nf]);
                }
        }
    }

    // epilogue
#pragma unroll
    for (int mf = 0; mf < 4; mf++) {
#pragma unroll
        for (int nf = 0; nf < 4; nf++) {
            int r = m0 + wm * 64 + mf * 16 + g;
            int cb = n0 + wn * 32 + nf * 8 + 2 * t;
            float v0 = acc[mf][nf][0], v1 = acc[mf][nf][1];
            float v2 = acc[mf][nf][2], v3 = acc[mf][nf][3];
            if (DO_COS) {
                float t0 = theta[cb & 63], t1 = theta[(cb + 1) & 63];
                v0 = cosf(v0 + t0); v1 = cosf(v1 + t1);
                v2 = cosf(v2 + t0); v3 = cosf(v3 + t1);
            }
            *(float2*)&C[(size_t)r * Ee + cb]       = float2{v0, v1};
            *(float2*)&C[(size_t)(r + 8) * Ee + cb] = float2{v2, v3};
        }
    }
}

// ------------------------- SIMT flash attention ------------------------------
#define APITCH 68
#define PPITCH 65
#define ATT_SMEM ((3*64*APITCH + 64*PPITCH + 3*64) * 4)

__global__ __launch_bounds__(256) void attn64(const float* __restrict__ q,
                                              const float* __restrict__ k,
                                              const float* __restrict__ v,
                                              __nv_bfloat16* __restrict__ chi,
                                              __nv_bfloat16* __restrict__ clo)
{
    extern __shared__ float sm[];
    float* Qt = sm;
    float* Kt = Qt + 64 * APITCH;
    float* Vs = Kt + 64 * APITCH;
    float* Ps = Vs + 64 * APITCH;
    float* mrow = Ps + 64 * PPITCH;
    float* lrow = mrow + 64;
    float* srow = lrow + 64;

    int tid = threadIdx.x;
    int txi = tid & 15, tyi = tid >> 4;
    int bh = blockIdx.y;
    int b = bh >> 4, h = bh & 15;
    int q0 = blockIdx.x * 64;
    size_t base = (size_t)b * Ss * Ee + (size_t)h * Dk;
    const float* qb = q + base;
    const float* kb = k + base;
    const float* vb = v + base;

    int lr = tid >> 2;
    int lc = (tid & 3) << 4;

    {
        const float* src = qb + (size_t)(q0 + lr) * Ee + lc;
#pragma unroll
        for (int u = 0; u < 4; u++) {
            float4 a = *(const float4*)(src + u * 4);
            int d = lc + u * 4;
            Qt[(d+0)*APITCH + lr] = a.x; Qt[(d+1)*APITCH + lr] = a.y;
            Qt[(d+2)*APITCH + lr] = a.z; Qt[(d+3)*APITCH + lr] = a.w;
        }
    }
    if (tid < 64) { mrow[tid] = -1e30f; lrow[tid] = 0.0f; }
    float o[4][4] = {};
    __syncthreads();

    for (int j0 = 0; j0 < Ss; j0 += 64) {
        {
            const float* ksrc = kb + (size_t)(j0 + lr) * Ee + lc;
            const float* vsrc = vb + (size_t)(j0 + lr) * Ee + lc;
#pragma unroll
            for (int u = 0; u < 4; u++) {
                float4 a = *(const float4*)(ksrc + u * 4);
                int d = lc + u * 4;
                Kt[(d+0)*APITCH + lr] = a.x; Kt[(d+1)*APITCH + lr] = a.y;
                Kt[(d+2)*APITCH + lr] = a.z; Kt[(d+3)*APITCH + lr] = a.w;
                float4 vv = *(const float4*)(vsrc + u * 4);
                *(float4*)(&Vs[lr*APITCH + d]) = vv;
            }
        }
        __syncthreads();

        float s[4][4] = {};
#pragma unroll
        for (int d = 0; d < 64; d++) {
            float4 a4 = *(const float4*)(&Qt[d*APITCH + (tyi << 2)]);
            float4 b4 = *(const float4*)(&Kt[d*APITCH + (txi << 2)]);
            float av[4] = {a4.x, a4.y, a4.z, a4.w};
            float bv[4] = {b4.x, b4.y, b4.z, b4.w};
#pragma unroll
            for (int i = 0; i < 4; i++)
#pragma unroll
                for (int j = 0; j < 4; j++)
                    s[i][j] = fmaf(av[i], bv[j], s[i][j]);
        }
#pragma unroll
        for (int i = 0; i < 4; i++)
#pragma unroll
            for (int j = 0; j < 4; j++)
                Ps[((tyi<<2)+i)*PPITCH + (txi<<2)+j] = s[i][j] * 0.125f;
        __syncthreads();

        {
            int r = tid >> 2;
            float* row = Ps + r * PPITCH + (tid & 3) * 16;
            float mx = -1e30f;
#pragma unroll
            for (int c = 0; c < 16; c++) mx = fmaxf(mx, row[c]);
            mx = fmaxf(mx, __shfl_xor_sync(0xffffffffu, mx, 1));
            mx = fmaxf(mx, __shfl_xor_sync(0xffffffffu, mx, 2));
            float mold = mrow[r];
            float mnew = fmaxf(mold, mx);
            float sum = 0.0f;
#pragma unroll
            for (int c = 0; c < 16; c++) {
                float p = __expf(row[c] - mnew);
                row[c] = p;
                sum += p;
            }
            sum += __shfl_xor_sync(0xffffffffu, sum, 1);
            sum += __shfl_xor_sync(0xffffffffu, sum, 2);
            if ((tid & 3) == 0) {
                float sc = __expf(mold - mnew);
                srow[r] = sc;
                lrow[r] = lrow[r] * sc + sum;
                mrow[r] = mnew;
            }
        }
        __syncthreads();

#pragma unroll
        for (int i = 0; i < 4; i++) {
            float sc = srow[(tyi << 2) + i];
#pragma unroll
            for (int j = 0; j < 4; j++) o[i][j] *= sc;
        }
#pragma unroll
        for (int j = 0; j < 64; j++) {
            float4 v4 = *(const float4*)(&Vs[j*APITCH + (txi << 2)]);
            float vv[4] = {v4.x, v4.y, v4.z, v4.w};
            float p[4];
#pragma unroll
            for (int i = 0; i < 4; i++) p[i] = Ps[((tyi<<2)+i)*PPITCH + j];
#pragma unroll
            for (int i = 0; i < 4; i++)
#pragma unroll
                for (int jj = 0; jj < 4; jj++)
                    o[i][jj] = fmaf(p[i], vv[jj], o[i][jj]);
        }
        __syncthreads();
    }

    // normalize and write ctx as bf16 hi/lo
#pragma unroll
    for (int i = 0; i < 4; i++) {
        int r = (tyi << 2) + i;
        float inv = 1.0f / lrow[r];
        size_t idx = (size_t)b * Ss * Ee + (size_t)(q0 + r) * Ee
                   + h * Dk + (txi << 2);
        __nv_bfloat16 hh[4], ll[4];
#pragma unroll
        for (int j = 0; j < 4; j++) {
            float val = o[i][j] * inv;
            hh[j] = __float2bfloat16(val);
            ll[j] = __float2bfloat16(val - __bfloat162float(hh[j]));
        }
        __nv_bfloat162* hp = (__nv_bfloat162*)(chi + idx);
        __nv_bfloat162* lp = (__nv_bfloat162*)(clo + idx);
        hp[0] = __nv_bfloat162{hh[0], hh[1]}; hp[1] = __nv_bfloat162{hh[2], hh[3]};
        lp[0] = __nv_bfloat162{ll[0], ll[1]}; lp[1] = __nv_bfloat162{ll[2], ll[3]};
    }
}

// ---------------------------------------------------------------------------
extern "C" void kernel_launch(void* const* d_in, const int* in_sizes, int n_in,
                              void* d_out, int out_size)
{
    const float* x     = (const float*)d_in[0];
    const float* Wq    = (const float*)d_in[1];
    const float* Wk    = (const float*)d_in[2];
    const float* Wv    = (const float*)d_in[3];
    const float* Wo    = (const float*)d_in[4];
    const float* theta = (const float*)d_in[5];
    float* out = (float*)d_out;

    float *qp, *kp, *vp;
    __nv_bfloat16 *xhi, *xlo, *chi, *clo, *whi, *wlo;
    cudaGetSymbolAddress((void**)&qp, g_q);
    cudaGetSymbolAddress((void**)&kp, g_k);
    cudaGetSymbolAddress((void**)&vp, g_v);
    cudaGetSymbolAddress((void**)&xhi, g_xhi);
    cudaGetSymbolAddress((void**)&xlo, g_xlo);
    cudaGetSymbolAddress((void**)&chi, g_chi);
    cudaGetSymbolAddress((void**)&clo, g_clo);
    cudaGetSymbolAddress((void**)&whi, g_whi);
    cudaGetSymbolAddress((void**)&wlo, g_wlo);

    cudaFuncSetAttribute(hmma_gemm<true>,
        cudaFuncAttributeMaxDynamicSharedMemorySize, GEMM_SMEM);
    cudaFuncSetAttribute(hmma_gemm<false>,
        cudaFuncAttributeMaxDynamicSharedMemorySize, GEMM_SMEM);
    cudaFuncSetAttribute(attn64,
        cudaFuncAttributeMaxDynamicSharedMemorySize, ATT_SMEM);

    int n4x = Mm * Ee / 4;
    int n4w = Ee * Ee / 4;
    split_kernel<<<(n4x + 255) / 256, 256>>>((const float4*)x,  xhi, xlo, n4x);
    split_kernel<<<(n4w + 255) / 256, 256>>>((const float4*)Wq, whi + 0*(size_t)Ee*Ee, wlo + 0*(size_t)Ee*Ee, n4w);
    split_kernel<<<(n4w + 255) / 256, 256>>>((const float4*)Wk, whi + 1*(size_t)Ee*Ee, wlo + 1*(size_t)Ee*Ee, n4w);
    split_kernel<<<(n4w + 255) / 256, 256>>>((const float4*)Wv, whi + 2*(size_t)Ee*Ee, wlo + 2*(size_t)Ee*Ee, n4w);
    split_kernel<<<(n4w + 255) / 256, 256>>>((const float4*)Wo, whi + 3*(size_t)Ee*Ee, wlo + 3*(size_t)Ee*Ee, n4w);

    dim3 blk(256);
    dim3 g1(Ee / 128, Mm / 128);   // (8, 64)
    hmma_gemm<true><<<g1, blk, GEMM_SMEM>>>(xhi, xlo,
        whi + 0*(size_t)Ee*Ee, wlo + 0*(size_t)Ee*Ee, theta, qp);
    hmma_gemm<true><<<g1, blk, GEMM_SMEM>>>(xhi, xlo,
        whi + 1*(size_t)Ee*Ee, wlo + 1*(size_t)Ee*Ee, theta, kp);
    hmma_gemm<true><<<g1, blk, GEMM_SMEM>>>(xhi, xlo,
        whi + 2*(size_t)Ee*Ee, wlo + 2*(size_t)Ee*Ee, theta, vp);

    dim3 g2(Ss / 64, Bb * Hh);
    attn64<<<g2, blk, ATT_SMEM>>>(qp, kp, vp, chi, clo);

    hmma_gemm<false><<<g1, blk, GEMM_SMEM>>>(chi, clo,
        whi + 3*(size_t)Ee*Ee, wlo + 3*(size_t)Ee*Ee, nullptr, out);
}

// round 4
// speedup vs baseline: 2.6565x; 2.0378x over previous
#include <cuda_runtime.h>
#include <cuda_bf16.h>
#include <math.h>
#include <stdint.h>

#define Bb 4
#define Ss 2048
#define Ee 1024
#define Hh 16
#define Dk 64
#define Mm (Bb*Ss)   /* 8192 */

// ------------------------- device scratch (no allocs) ----------------------
__device__ __nv_bfloat16 g_xhi[Mm*Ee];
__device__ __nv_bfloat16 g_xlo[Mm*Ee];
__device__ __nv_bfloat16 g_qhi[Mm*Ee];
__device__ __nv_bfloat16 g_qlo[Mm*Ee];
__device__ __nv_bfloat16 g_khi[Mm*Ee];
__device__ __nv_bfloat16 g_klo[Mm*Ee];
__device__ __nv_bfloat16 g_vhi[Mm*Ee];
__device__ __nv_bfloat16 g_vlo[Mm*Ee];
__device__ __nv_bfloat16 g_chi[Mm*Ee];
__device__ __nv_bfloat16 g_clo[Mm*Ee];
__device__ __nv_bfloat16 g_whi[4*Ee*Ee];
__device__ __nv_bfloat16 g_wlo[4*Ee*Ee];

// ------------------------- helpers ------------------------------------------
__device__ __forceinline__ void mma16816(float* d, const uint32_t* a,
                                         const uint32_t* b)
{
    asm volatile(
        "mma.sync.aligned.m16n8k16.row.col.f32.bf16.bf16.f32 "
        "{%0,%1,%2,%3}, {%4,%5,%6,%7}, {%8,%9}, {%0,%1,%2,%3};"
        : "+f"(d[0]), "+f"(d[1]), "+f"(d[2]), "+f"(d[3])
        : "r"(a[0]), "r"(a[1]), "r"(a[2]), "r"(a[3]), "r"(b[0]), "r"(b[1]));
}
__device__ __forceinline__ uint32_t smem_u32(const void* p) {
    uint32_t a;
    asm("{ .reg .u64 t; cvta.to.shared.u64 t, %1; cvt.u32.u64 %0, t; }"
        : "=r"(a) : "l"(p));
    return a;
}
__device__ __forceinline__ void cpa16(uint32_t s, const void* g) {
    asm volatile("cp.async.cg.shared.global [%0], [%1], 16;" :: "r"(s), "l"(g));
}
#define CPA_COMMIT() asm volatile("cp.async.commit_group;" ::: "memory")
#define CPA_WAIT1()  asm volatile("cp.async.wait_group 1;" ::: "memory")
#define CPA_WAIT0()  asm volatile("cp.async.wait_group 0;" ::: "memory")

__device__ __forceinline__ uint32_t pack_hi(float x, float y) {
    __nv_bfloat162 h = __floats2bfloat162_rn(x, y);
    return *(uint32_t*)&h;
}
__device__ __forceinline__ uint32_t pack_lo(float x, float y, uint32_t hiu) {
    __nv_bfloat162 h = *(__nv_bfloat162*)&hiu;
    __nv_bfloat162 l = __floats2bfloat162_rn(x - __bfloat162float(h.x),
                                             y - __bfloat162float(h.y));
    return *(uint32_t*)&l;
}

// ------------------------- fp32 -> bf16 hi/lo split --------------------------
__global__ __launch_bounds__(256) void split_kernel(const float4* __restrict__ src,
                                                    __nv_bfloat16* __restrict__ hi,
                                                    __nv_bfloat16* __restrict__ lo,
                                                    int n4)
{
    int i = blockIdx.x * 256 + threadIdx.x;
    if (i >= n4) return;
    float4 v = src[i];
    uint32_t h0 = pack_hi(v.x, v.y), h1 = pack_hi(v.z, v.w);
    uint32_t l0 = pack_lo(v.x, v.y, h0), l1 = pack_lo(v.z, v.w, h1);
    uint32_t* hp = (uint32_t*)(hi + (size_t)i * 4);
    uint32_t* lp = (uint32_t*)(lo + (size_t)i * 4);
    hp[0] = h0; hp[1] = h1; lp[0] = l0; lp[1] = l1;
}

// ------------------------- HMMA split-bf16 GEMM (cp.async pipelined) ---------
// C = A[M,1024] @ W[1024,1024]^T ; DO_COS -> bf16 hi/lo outputs, else f32.
#define PCH 72
#define TILE_B (128 * PCH * 2)            /* 18432 bytes per array */
#define GEMM_SMEM (TILE_B * 4 * 2)        /* 147456 */

template<bool DO_COS>
__global__ __launch_bounds__(256, 1) void hmma_gemm(
    const __nv_bfloat16* __restrict__ Ahi, const __nv_bfloat16* __restrict__ Alo,
    const __nv_bfloat16* __restrict__ Whi, const __nv_bfloat16* __restrict__ Wlo,
    const float* __restrict__ theta,
    float* __restrict__ C,
    __nv_bfloat16* __restrict__ OH, __nv_bfloat16* __restrict__ OL)
{
    extern __shared__ __align__(16) char smem[];
    uint32_t sb = smem_u32(smem);

    int tid = threadIdx.x, wid = tid >> 5, lane = tid & 31;
    int wm = wid & 1, wn = wid >> 1;
    int g = lane >> 2, t = lane & 3;
    int m0 = blockIdx.y * 128, n0 = blockIdx.x * 128;

    float acc[4][4][4] = {};

    // cp.async issue for chunk c into buffer bs
    auto issue = [&](int c, int bs) {
        uint32_t b0 = sb + bs * (TILE_B * 4);
#pragma unroll
        for (int u = 0; u < 4; u++) {
            int unit = tid + u * 256;
            int row = unit >> 3, seg = unit & 7;
            size_t gA = (size_t)(m0 + row) * Ee + c * 64 + seg * 8;
            size_t gW = (size_t)(n0 + row) * Ee + c * 64 + seg * 8;
            uint32_t so = (uint32_t)(row * PCH + seg * 8) * 2;
            cpa16(b0 + so,              Ahi + gA);
            cpa16(b0 + TILE_B + so,     Alo + gA);
            cpa16(b0 + 2 * TILE_B + so, Whi + gW);
            cpa16(b0 + 3 * TILE_B + so, Wlo + gW);
        }
    };

    issue(0, 0);
    CPA_COMMIT();

    for (int c = 0; c < 16; c++) {
        if (c < 15) { issue(c + 1, (c + 1) & 1); CPA_COMMIT(); CPA_WAIT1(); }
        else CPA_WAIT0();
        __syncthreads();

        const __nv_bfloat16* sAh = (const __nv_bfloat16*)(smem + (c & 1) * (TILE_B * 4));
        const __nv_bfloat16* sAl = sAh + 128 * PCH;
        const __nv_bfloat16* sWh = sAl + 128 * PCH;
        const __nv_bfloat16* sWl = sWh + 128 * PCH;

#pragma unroll
        for (int ks = 0; ks < 4; ks++) {
            int cc = ks * 16 + 2 * t;
            uint32_t ah[4][4], al[4][4];
#pragma unroll
            for (int mf = 0; mf < 4; mf++) {
                int r = wm * 64 + mf * 16 + g;
                ah[mf][0] = *(const uint32_t*)&sAh[r * PCH + cc];
                ah[mf][1] = *(const uint32_t*)&sAh[(r + 8) * PCH + cc];
                ah[mf][2] = *(const uint32_t*)&sAh[r * PCH + cc + 8];
                ah[mf][3] = *(const uint32_t*)&sAh[(r + 8) * PCH + cc + 8];
                al[mf][0] = *(const uint32_t*)&sAl[r * PCH + cc];
                al[mf][1] = *(const uint32_t*)&sAl[(r + 8) * PCH + cc];
                al[mf][2] = *(const uint32_t*)&sAl[r * PCH + cc + 8];
                al[mf][3] = *(const uint32_t*)&sAl[(r + 8) * PCH + cc + 8];
            }
#pragma unroll
            for (int nf = 0; nf < 4; nf++) {
                int r = wn * 32 + nf * 8 + g;
                uint32_t bh[2], bl[2];
                bh[0] = *(const uint32_t*)&sWh[r * PCH + cc];
                bh[1] = *(const uint32_t*)&sWh[r * PCH + cc + 8];
                bl[0] = *(const uint32_t*)&sWl[r * PCH + cc];
                bl[1] = *(const uint32_t*)&sWl[r * PCH + cc + 8];
#pragma unroll
                for (int mf = 0; mf < 4; mf++) {
                    mma16816(acc[mf][nf], ah[mf], bh);
                    mma16816(acc[mf][nf], ah[mf], bl);
                    mma16816(acc[mf][nf], al[mf], bh);
                }
            }
        }
        __syncthreads();
    }

    // epilogue
#pragma unroll
    for (int mf = 0; mf < 4; mf++) {
#pragma unroll
        for (int nf = 0; nf < 4; nf++) {
            int r = m0 + wm * 64 + mf * 16 + g;
            int cb = n0 + wn * 32 + nf * 8 + 2 * t;
            float v0 = acc[mf][nf][0], v1 = acc[mf][nf][1];
            float v2 = acc[mf][nf][2], v3 = acc[mf][nf][3];
            if (DO_COS) {
                float t0 = theta[cb & 63], t1 = theta[(cb + 1) & 63];
                v0 = cosf(v0 + t0); v1 = cosf(v1 + t1);
                v2 = cosf(v2 + t0); v3 = cosf(v3 + t1);
                uint32_t h0 = pack_hi(v0, v1), h1 = pack_hi(v2, v3);
                *(uint32_t*)&OH[(size_t)r * Ee + cb]       = h0;
                *(uint32_t*)&OH[(size_t)(r + 8) * Ee + cb] = h1;
                *(uint32_t*)&OL[(size_t)r * Ee + cb]       = pack_lo(v0, v1, h0);
                *(uint32_t*)&OL[(size_t)(r + 8) * Ee + cb] = pack_lo(v2, v3, h1);
            } else {
                *(float2*)&C[(size_t)r * Ee + cb]       = float2{v0, v1};
                *(float2*)&C[(size_t)(r + 8) * Ee + cb] = float2{v2, v3};
            }
        }
    }
}

// ------------------------- HMMA flash attention ------------------------------
// CTA: 128 q-rows, 8 warps x 16 rows, KV tiles of 128. Warp-local softmax.
#define PK 72
#define PV 138
#define KBYTES (128 * PK * 2)           /* 18432 */
#define VBYTES (64 * PV * 2)            /* 17664 */
#define ATT_SMEM (2*KBYTES + 2*VBYTES)  /* 72192 */

__global__ __launch_bounds__(256, 1) void attn_mma(
    const __nv_bfloat16* __restrict__ qhi, const __nv_bfloat16* __restrict__ qlo,
    const __nv_bfloat16* __restrict__ khi, const __nv_bfloat16* __restrict__ klo,
    const __nv_bfloat16* __restrict__ vhi, const __nv_bfloat16* __restrict__ vlo,
    __nv_bfloat16* __restrict__ chi, __nv_bfloat16* __restrict__ clo)
{
    extern __shared__ __align__(16) char smem[];
    __nv_bfloat16* Kh  = (__nv_bfloat16*)smem;
    __nv_bfloat16* Kl  = Kh + 128 * PK;
    __nv_bfloat16* Vth = Kl + 128 * PK;
    __nv_bfloat16* Vtl = Vth + 64 * PV;

    int tid = threadIdx.x, wid = tid >> 5, lane = tid & 31;
    int g = lane >> 2, t = lane & 3;
    int bh = blockIdx.y;
    int b = bh >> 4, h = bh & 15;
    int q0 = blockIdx.x * 128;
    size_t base = (size_t)b * Ss * Ee + (size_t)h * Dk;

    // Q fragments in registers (hi/lo), 4 k-steps
    uint32_t qh[4][4], ql[4][4];
    {
        size_t r0 = base + (size_t)(q0 + wid * 16 + g) * Ee;
        size_t r1 = r0 + 8 * (size_t)Ee;
#pragma unroll
        for (int ks = 0; ks < 4; ks++) {
            int c0 = ks * 16 + 2 * t;
            qh[ks][0] = *(const uint32_t*)&qhi[r0 + c0];
            qh[ks][1] = *(const uint32_t*)&qhi[r1 + c0];
            qh[ks][2] = *(const uint32_t*)&qhi[r0 + c0 + 8];
            qh[ks][3] = *(const uint32_t*)&qhi[r1 + c0 + 8];
            ql[ks][0] = *(const uint32_t*)&qlo[r0 + c0];
            ql[ks][1] = *(const uint32_t*)&qlo[r1 + c0];
            ql[ks][2] = *(const uint32_t*)&qlo[r0 + c0 + 8];
            ql[ks][3] = *(const uint32_t*)&qlo[r1 + c0 + 8];
        }
    }

    float m0 = -1e30f, m1 = -1e30f, l0 = 0.0f, l1 = 0.0f;
    float out[8][4] = {};

    for (int j0 = 0; j0 < Ss; j0 += 128) {
        __syncthreads();
        // load K tile [128 keys x 64 d] hi/lo
#pragma unroll
        for (int u = 0; u < 4; u++) {
            int unit = tid + u * 256;
            int row = unit >> 3, seg = unit & 7;
            size_t gk = base + (size_t)(j0 + row) * Ee + seg * 8;
            *(uint4*)&Kh[row * PK + seg * 8] = *(const uint4*)&khi[gk];
            *(uint4*)&Kl[row * PK + seg * 8] = *(const uint4*)&klo[gk];
        }
        // load V tile transposed: Vt[d][key]
#pragma unroll
        for (int u = 0; u < 16; u++) {
            int unit = tid + u * 256;          // 0..4095
            int key = unit >> 5, dp = unit & 31;
            size_t gv = base + (size_t)(j0 + key) * Ee + 2 * dp;
            __nv_bfloat162 vh = *(const __nv_bfloat162*)&vhi[gv];
            __nv_bfloat162 vl = *(const __nv_bfloat162*)&vlo[gv];
            Vth[(2 * dp) * PV + key]     = vh.x;
            Vth[(2 * dp + 1) * PV + key] = vh.y;
            Vtl[(2 * dp) * PV + key]     = vl.x;
            Vtl[(2 * dp + 1) * PV + key] = vl.y;
        }
        __syncthreads();

        // QK^T -> s[16][4]
        float s[16][4] = {};
#pragma unroll
        for (int ks = 0; ks < 4; ks++) {
            int cc = ks * 16 + 2 * t;
#pragma unroll
            for (int nf = 0; nf < 16; nf++) {
                int r = nf * 8 + g;
                uint32_t bhr[2], blr[2];
                bhr[0] = *(const uint32_t*)&Kh[r * PK + cc];
                bhr[1] = *(const uint32_t*)&Kh[r * PK + cc + 8];
                blr[0] = *(const uint32_t*)&Kl[r * PK + cc];
                blr[1] = *(const uint32_t*)&Kl[r * PK + cc + 8];
                mma16816(s[nf], qh[ks], bhr);
                mma16816(s[nf], qh[ks], blr);
                mma16816(s[nf], ql[ks], bhr);
            }
        }

        // warp-local online softmax (scale 0.125 folded into exp)
        float mx0 = -1e30f, mx1 = -1e30f;
#pragma unroll
        for (int nf = 0; nf < 16; nf++) {
            mx0 = fmaxf(mx0, fmaxf(s[nf][0], s[nf][1]));
            mx1 = fmaxf(mx1, fmaxf(s[nf][2], s[nf][3]));
        }
        mx0 = fmaxf(mx0, __shfl_xor_sync(0xffffffffu, mx0, 1));
        mx0 = fmaxf(mx0, __shfl_xor_sync(0xffffffffu, mx0, 2));
        mx1 = fmaxf(mx1, __shfl_xor_sync(0xffffffffu, mx1, 1));
        mx1 = fmaxf(mx1, __shfl_xor_sync(0xffffffffu, mx1, 2));
        float mn0 = fmaxf(m0, mx0), mn1 = fmaxf(m1, mx1);
        float sc0 = __expf(0.125f * (m0 - mn0));
        float sc1 = __expf(0.125f * (m1 - mn1));
        float sum0 = 0.0f, sum1 = 0.0f;
#pragma unroll
        for (int nf = 0; nf < 16; nf++) {
            s[nf][0] = __expf(0.125f * (s[nf][0] - mn0));
            s[nf][1] = __expf(0.125f * (s[nf][1] - mn0));
            s[nf][2] = __expf(0.125f * (s[nf][2] - mn1));
            s[nf][3] = __expf(0.125f * (s[nf][3] - mn1));
            sum0 += s[nf][0] + s[nf][1];
            sum1 += s[nf][2] + s[nf][3];
        }
        sum0 += __shfl_xor_sync(0xffffffffu, sum0, 1);
        sum0 += __shfl_xor_sync(0xffffffffu, sum0, 2);
        sum1 += __shfl_xor_sync(0xffffffffu, sum1, 1);
        sum1 += __shfl_xor_sync(0xffffffffu, sum1, 2);
        l0 = l0 * sc0 + sum0;
        l1 = l1 * sc1 + sum1;
        m0 = mn0; m1 = mn1;
#pragma unroll
        for (int nfo = 0; nfo < 8; nfo++) {
            out[nfo][0] *= sc0; out[nfo][1] *= sc0;
            out[nfo][2] *= sc1; out[nfo][3] *= sc1;
        }

        // PV: O += P @ V   (P from regs, split hi/lo)
#pragma unroll
        for (int ks2 = 0; ks2 < 8; ks2++) {
            uint32_t ah[4], al[4];
            ah[0] = pack_hi(s[2*ks2][0],   s[2*ks2][1]);
            ah[1] = pack_hi(s[2*ks2][2],   s[2*ks2][3]);
            ah[2] = pack_hi(s[2*ks2+1][0], s[2*ks2+1][1]);
            ah[3] = pack_hi(s[2*ks2+1][2], s[2*ks2+1][3]);
            al[0] = pack_lo(s[2*ks2][0],   s[2*ks2][1],   ah[0]);
            al[1] = pack_lo(s[2*ks2][2],   s[2*ks2][3],   ah[1]);
            al[2] = pack_lo(s[2*ks2+1][0], s[2*ks2+1][1], ah[2]);
            al[3] = pack_lo(s[2*ks2+1][2], s[2*ks2+1][3], ah[3]);
            int cc = ks2 * 16 + 2 * t;
#pragma unroll
            for (int nfo = 0; nfo < 8; nfo++) {
                int r = nfo * 8 + g;
                uint32_t bvh[2], bvl[2];
                bvh[0] = *(const uint32_t*)&Vth[r * PV + cc];
                bvh[1] = *(const uint32_t*)&Vth[r * PV + cc + 8];
                bvl[0] = *(const uint32_t*)&Vtl[r * PV + cc];
                bvl[1] = *(const uint32_t*)&Vtl[r * PV + cc + 8];
                mma16816(out[nfo], ah, bvh);
                mma16816(out[nfo], ah, bvl);
                mma16816(out[nfo], al, bvh);
            }
        }
    }

    // normalize + write ctx hi/lo
    float inv0 = 1.0f / l0, inv1 = 1.0f / l1;
    size_t r0 = base + (size_t)(q0 + wid * 16 + g) * Ee;
    size_t r1 = r0 + 8 * (size_t)Ee;
#pragma unroll
    for (int nfo = 0; nfo < 8; nfo++) {
        int d = nfo * 8 + 2 * t;
        float v0 = out[nfo][0] * inv0, v1 = out[nfo][1] * inv0;
        float v2 = out[nfo][2] * inv1, v3 = out[nfo][3] * inv1;
        uint32_t h0 = pack_hi(v0, v1), h1 = pack_hi(v2, v3);
        *(uint32_t*)&chi[r0 + d] = h0;
        *(uint32_t*)&chi[r1 + d] = h1;
        *(uint32_t*)&clo[r0 + d] = pack_lo(v0, v1, h0);
        *(uint32_t*)&clo[r1 + d] = pack_lo(v2, v3, h1);
    }
}

// ---------------------------------------------------------------------------
extern "C" void kernel_launch(void* const* d_in, const int* in_sizes, int n_in,
                              void* d_out, int out_size)
{
    const float* x     = (const float*)d_in[0];
    const float* Wq    = (const float*)d_in[1];
    const float* Wk    = (const float*)d_in[2];
    const float* Wv    = (const float*)d_in[3];
    const float* Wo    = (const float*)d_in[4];
    const float* theta = (const float*)d_in[5];
    float* out = (float*)d_out;

    __nv_bfloat16 *xhi, *xlo, *qhi, *qlo, *khi, *klo, *vhi, *vlo,
                  *chi, *clo, *whi, *wlo;
    cudaGetSymbolAddress((void**)&xhi, g_xhi);
    cudaGetSymbolAddress((void**)&xlo, g_xlo);
    cudaGetSymbolAddress((void**)&qhi, g_qhi);
    cudaGetSymbolAddress((void**)&qlo, g_qlo);
    cudaGetSymbolAddress((void**)&khi, g_khi);
    cudaGetSymbolAddress((void**)&klo, g_klo);
    cudaGetSymbolAddress((void**)&vhi, g_vhi);
    cudaGetSymbolAddress((void**)&vlo, g_vlo);
    cudaGetSymbolAddress((void**)&chi, g_chi);
    cudaGetSymbolAddress((void**)&clo, g_clo);
    cudaGetSymbolAddress((void**)&whi, g_whi);
    cudaGetSymbolAddress((void**)&wlo, g_wlo);

    cudaFuncSetAttribute(hmma_gemm<true>,
        cudaFuncAttributeMaxDynamicSharedMemorySize, GEMM_SMEM);
    cudaFuncSetAttribute(hmma_gemm<false>,
        cudaFuncAttributeMaxDynamicSharedMemorySize, GEMM_SMEM);
    cudaFuncSetAttribute(attn_mma,
        cudaFuncAttributeMaxDynamicSharedMemorySize, ATT_SMEM);

    int n4x = Mm * Ee / 4;
    int n4w = Ee * Ee / 4;
    split_kernel<<<(n4x + 255) / 256, 256>>>((const float4*)x,  xhi, xlo, n4x);
    split_kernel<<<(n4w + 255) / 256, 256>>>((const float4*)Wq, whi + 0*(size_t)Ee*Ee, wlo + 0*(size_t)Ee*Ee, n4w);
    split_kernel<<<(n4w + 255) / 256, 256>>>((const float4*)Wk, whi + 1*(size_t)Ee*Ee, wlo + 1*(size_t)Ee*Ee, n4w);
    split_kernel<<<(n4w + 255) / 256, 256>>>((const float4*)Wv, whi + 2*(size_t)Ee*Ee, wlo + 2*(size_t)Ee*Ee, n4w);
    split_kernel<<<(n4w + 255) / 256, 256>>>((const float4*)Wo, whi + 3*(size_t)Ee*Ee, wlo + 3*(size_t)Ee*Ee, n4w);

    dim3 blk(256);
    dim3 g1(Ee / 128, Mm / 128);   // (8, 64)
    hmma_gemm<true><<<g1, blk, GEMM_SMEM>>>(xhi, xlo,
        whi + 0*(size_t)Ee*Ee, wlo + 0*(size_t)Ee*Ee, theta, nullptr, qhi, qlo);
    hmma_gemm<true><<<g1, blk, GEMM_SMEM>>>(xhi, xlo,
        whi + 1*(size_t)Ee*Ee, wlo + 1*(size_t)Ee*Ee, theta, nullptr, khi, klo);
    hmma_gemm<true><<<g1, blk, GEMM_SMEM>>>(xhi, xlo,
        whi + 2*(size_t)Ee*Ee, wlo + 2*(size_t)Ee*Ee, theta, nullptr, vhi, vlo);

    dim3 g2(Ss / 128, Bb * Hh);    // (16, 64)
    attn_mma<<<g2, blk, ATT_SMEM>>>(qhi, qlo, khi, klo, vhi, vlo, chi, clo);

    hmma_gemm<false><<<g1, blk, GEMM_SMEM>>>(chi, clo,
        whi + 3*(size_t)Ee*Ee, wlo + 3*(size_t)Ee*Ee, nullptr, out, nullptr, nullptr);
}

// round 5
// speedup vs baseline: 3.1870x; 1.1997x over previous
#include <cuda_runtime.h>
#include <cuda_bf16.h>
#include <math.h>
#include <stdint.h>

#define Bb 4
#define Ss 2048
#define Ee 1024
#define Hh 16
#define Dk 64
#define Mm (Bb*Ss)   /* 8192 */

// ------------------------- device scratch (no allocs) ----------------------
__device__ __nv_bfloat16 g_xhi[Mm*Ee];
__device__ __nv_bfloat16 g_xlo[Mm*Ee];
__device__ __nv_bfloat16 g_qhi[Mm*Ee];
__device__ __nv_bfloat16 g_qlo[Mm*Ee];
__device__ __nv_bfloat16 g_khi[Mm*Ee];
__device__ __nv_bfloat16 g_klo[Mm*Ee];
__device__ __nv_bfloat16 g_vhi[Mm*Ee];
__device__ __nv_bfloat16 g_vlo[Mm*Ee];
__device__ __nv_bfloat16 g_chi[Mm*Ee];
__device__ __nv_bfloat16 g_clo[Mm*Ee];
__device__ __nv_bfloat16 g_whi[4*Ee*Ee];
__device__ __nv_bfloat16 g_wlo[4*Ee*Ee];

// ------------------------- helpers ------------------------------------------
__device__ __forceinline__ void mma16816(float* d, const uint32_t* a,
                                         const uint32_t* b)
{
    asm volatile(
        "mma.sync.aligned.m16n8k16.row.col.f32.bf16.bf16.f32 "
        "{%0,%1,%2,%3}, {%4,%5,%6,%7}, {%8,%9}, {%0,%1,%2,%3};"
        : "+f"(d[0]), "+f"(d[1]), "+f"(d[2]), "+f"(d[3])
        : "r"(a[0]), "r"(a[1]), "r"(a[2]), "r"(a[3]), "r"(b[0]), "r"(b[1]));
}
__device__ __forceinline__ void ldsm_x4(uint32_t* r, uint32_t addr) {
    asm volatile("ldmatrix.sync.aligned.m8n8.x4.shared.b16 {%0,%1,%2,%3}, [%4];"
        : "=r"(r[0]), "=r"(r[1]), "=r"(r[2]), "=r"(r[3]) : "r"(addr));
}
__device__ __forceinline__ void ldsm_x4_t(uint32_t* r, uint32_t addr) {
    asm volatile("ldmatrix.sync.aligned.m8n8.x4.trans.shared.b16 {%0,%1,%2,%3}, [%4];"
        : "=r"(r[0]), "=r"(r[1]), "=r"(r[2]), "=r"(r[3]) : "r"(addr));
}
__device__ __forceinline__ uint32_t smem_u32(const void* p) {
    uint32_t a;
    asm("{ .reg .u64 t; cvta.to.shared.u64 t, %1; cvt.u32.u64 %0, t; }"
        : "=r"(a) : "l"(p));
    return a;
}
__device__ __forceinline__ void cpa16(uint32_t s, const void* g) {
    asm volatile("cp.async.cg.shared.global [%0], [%1], 16;" :: "r"(s), "l"(g));
}
#define CPA_COMMIT() asm volatile("cp.async.commit_group;" ::: "memory")
#define CPA_WAIT1()  asm volatile("cp.async.wait_group 1;" ::: "memory")
#define CPA_WAIT0()  asm volatile("cp.async.wait_group 0;" ::: "memory")

__device__ __forceinline__ uint32_t pack_hi(float x, float y) {
    __nv_bfloat162 h = __floats2bfloat162_rn(x, y);
    return *(uint32_t*)&h;
}
__device__ __forceinline__ uint32_t pack_lo(float x, float y, uint32_t hiu) {
    __nv_bfloat162 h = *(__nv_bfloat162*)&hiu;
    __nv_bfloat162 l = __floats2bfloat162_rn(x - __bfloat162float(h.x),
                                             y - __bfloat162float(h.y));
    return *(uint32_t*)&l;
}

// ------------------------- fp32 -> bf16 hi/lo split --------------------------
__global__ __launch_bounds__(256) void split_kernel(const float4* __restrict__ src,
                                                    __nv_bfloat16* __restrict__ hi,
                                                    __nv_bfloat16* __restrict__ lo,
                                                    int n4)
{
    int i = blockIdx.x * 256 + threadIdx.x;
    if (i >= n4) return;
    float4 v = src[i];
    uint32_t h0 = pack_hi(v.x, v.y), h1 = pack_hi(v.z, v.w);
    uint32_t l0 = pack_lo(v.x, v.y, h0), l1 = pack_lo(v.z, v.w, h1);
    uint32_t* hp = (uint32_t*)(hi + (size_t)i * 4);
    uint32_t* lp = (uint32_t*)(lo + (size_t)i * 4);
    hp[0] = h0; hp[1] = h1; lp[0] = l0; lp[1] = l1;
}

// ------------------------- HMMA split-bf16 GEMM (cp.async + ldmatrix) --------
#define PCH 72
#define TILE_B (128 * PCH * 2)            /* 18432 bytes per array */
#define GEMM_SMEM (TILE_B * 4 * 2)        /* 147456 */

template<bool DO_COS>
__global__ __launch_bounds__(256, 1) void hmma_gemm(
    const __nv_bfloat16* __restrict__ Ahi, const __nv_bfloat16* __restrict__ Alo,
    const __nv_bfloat16* __restrict__ Whi, const __nv_bfloat16* __restrict__ Wlo,
    const float* __restrict__ theta,
    float* __restrict__ C,
    __nv_bfloat16* __restrict__ OH, __nv_bfloat16* __restrict__ OL)
{
    extern __shared__ __align__(16) char smem[];
    uint32_t sb = smem_u32(smem);

    int tid = threadIdx.x, wid = tid >> 5, lane = tid & 31;
    int wm = wid & 1, wn = wid >> 1;
    int g = lane >> 2, t = lane & 3;
    int lm = lane >> 3, li = lane & 7;
    int m0 = blockIdx.y * 128, n0 = blockIdx.x * 128;

    float acc[4][4][4] = {};

    auto issue = [&](int c, int bs) {
        uint32_t b0 = sb + bs * (TILE_B * 4);
#pragma unroll
        for (int u = 0; u < 4; u++) {
            int unit = tid + u * 256;
            int row = unit >> 3, seg = unit & 7;
            size_t gA = (size_t)(m0 + row) * Ee + c * 64 + seg * 8;
            size_t gW = (size_t)(n0 + row) * Ee + c * 64 + seg * 8;
            uint32_t so = (uint32_t)(row * PCH + seg * 8) * 2;
            cpa16(b0 + so,              Ahi + gA);
            cpa16(b0 + TILE_B + so,     Alo + gA);
            cpa16(b0 + 2 * TILE_B + so, Whi + gW);
            cpa16(b0 + 3 * TILE_B + so, Wlo + gW);
        }
    };

    issue(0, 0);
    CPA_COMMIT();

    for (int c = 0; c < 16; c++) {
        if (c < 15) { issue(c + 1, (c + 1) & 1); CPA_COMMIT(); CPA_WAIT1(); }
        else CPA_WAIT0();
        __syncthreads();

        uint32_t bufA = sb + (c & 1) * (TILE_B * 4);
        uint32_t bufW = bufA + 2 * TILE_B;

#pragma unroll
        for (int ks = 0; ks < 4; ks++) {
            uint32_t ah[4][4], al[4][4];
#pragma unroll
            for (int mf = 0; mf < 4; mf++) {
                uint32_t ad = bufA +
                    (uint32_t)(((wm * 64 + mf * 16 + (lm & 1) * 8 + li) * PCH)
                               + ks * 16 + (lm >> 1) * 8) * 2;
                ldsm_x4(ah[mf], ad);
                ldsm_x4(al[mf], ad + TILE_B);
            }
#pragma unroll
            for (int nfp = 0; nfp < 2; nfp++) {
                uint32_t bd = bufW +
                    (uint32_t)(((wn * 32 + (nfp * 2 + (lm >> 1)) * 8 + li) * PCH)
                               + ks * 16 + (lm & 1) * 8) * 2;
                uint32_t bh[4], bl[4];
                ldsm_x4(bh, bd);
                ldsm_x4(bl, bd + TILE_B);
#pragma unroll
                for (int mf = 0; mf < 4; mf++) {
                    mma16816(acc[mf][nfp*2],   ah[mf], bh);
                    mma16816(acc[mf][nfp*2],   ah[mf], bl);
                    mma16816(acc[mf][nfp*2],   al[mf], bh);
                    mma16816(acc[mf][nfp*2+1], ah[mf], bh + 2);
                    mma16816(acc[mf][nfp*2+1], ah[mf], bl + 2);
                    mma16816(acc[mf][nfp*2+1], al[mf], bh + 2);
                }
            }
        }
        __syncthreads();
    }

    // epilogue
#pragma unroll
    for (int mf = 0; mf < 4; mf++) {
#pragma unroll
        for (int nf = 0; nf < 4; nf++) {
            int r = m0 + wm * 64 + mf * 16 + g;
            int cb = n0 + wn * 32 + nf * 8 + 2 * t;
            float v0 = acc[mf][nf][0], v1 = acc[mf][nf][1];
            float v2 = acc[mf][nf][2], v3 = acc[mf][nf][3];
            if (DO_COS) {
                float t0 = theta[cb & 63], t1 = theta[(cb + 1) & 63];
                v0 = cosf(v0 + t0); v1 = cosf(v1 + t1);
                v2 = cosf(v2 + t0); v3 = cosf(v3 + t1);
                uint32_t h0 = pack_hi(v0, v1), h1 = pack_hi(v2, v3);
                *(uint32_t*)&OH[(size_t)r * Ee + cb]       = h0;
                *(uint32_t*)&OH[(size_t)(r + 8) * Ee + cb] = h1;
                *(uint32_t*)&OL[(size_t)r * Ee + cb]       = pack_lo(v0, v1, h0);
                *(uint32_t*)&OL[(size_t)(r + 8) * Ee + cb] = pack_lo(v2, v3, h1);
            } else {
                *(float2*)&C[(size_t)r * Ee + cb]       = float2{v0, v1};
                *(float2*)&C[(size_t)(r + 8) * Ee + cb] = float2{v2, v3};
            }
        }
    }
}

// ------------------------- HMMA flash attention (cp.async + ldmatrix) --------
// Per stage: Kh | Kl | Vh | Vl, each 128 rows x 64 d, pitch 72 bf16.
#define PKV 72
#define KVB (128 * PKV * 2)              /* 18432 */
#define STAGEB (KVB * 4)                 /* 73728 */
#define ATT_SMEM (STAGEB * 2)            /* 147456 */

__global__ __launch_bounds__(256, 1) void attn_mma(
    const __nv_bfloat16* __restrict__ qhi, const __nv_bfloat16* __restrict__ qlo,
    const __nv_bfloat16* __restrict__ khi, const __nv_bfloat16* __restrict__ klo,
    const __nv_bfloat16* __restrict__ vhi, const __nv_bfloat16* __restrict__ vlo,
    __nv_bfloat16* __restrict__ chi, __nv_bfloat16* __restrict__ clo)
{
    extern __shared__ __align__(16) char smem[];
    uint32_t sb = smem_u32(smem);

    int tid = threadIdx.x, wid = tid >> 5, lane = tid & 31;
    int g = lane >> 2, t = lane & 3;
    int lm = lane >> 3, li = lane & 7;
    int bh_ = blockIdx.y;
    int b = bh_ >> 4, h = bh_ & 15;
    int q0 = blockIdx.x * 128;
    size_t base = (size_t)b * Ss * Ee + (size_t)h * Dk;

    // Q fragments (hi/lo), 4 k-steps
    uint32_t qh[4][4], ql[4][4];
    {
        size_t r0 = base + (size_t)(q0 + wid * 16 + g) * Ee;
        size_t r1 = r0 + 8 * (size_t)Ee;
#pragma unroll
        for (int ks = 0; ks < 4; ks++) {
            int c0 = ks * 16 + 2 * t;
            qh[ks][0] = *(const uint32_t*)&qhi[r0 + c0];
            qh[ks][1] = *(const uint32_t*)&qhi[r1 + c0];
            qh[ks][2] = *(const uint32_t*)&qhi[r0 + c0 + 8];
            qh[ks][3] = *(const uint32_t*)&qhi[r1 + c0 + 8];
            ql[ks][0] = *(const uint32_t*)&qlo[r0 + c0];
            ql[ks][1] = *(const uint32_t*)&qlo[r1 + c0];
            ql[ks][2] = *(const uint32_t*)&qlo[r0 + c0 + 8];
            ql[ks][3] = *(const uint32_t*)&qlo[r1 + c0 + 8];
        }
    }

    auto issue = [&](int j0, int s) {
        uint32_t b0 = sb + s * STAGEB;
#pragma unroll
        for (int u = 0; u < 4; u++) {
            int unit = tid + u * 256;
            int row = unit >> 3, seg = unit & 7;
            size_t gk = base + (size_t)(j0 + row) * Ee + seg * 8;
            uint32_t so = (uint32_t)(row * PKV + seg * 8) * 2;
            cpa16(b0 + so,           khi + gk);
            cpa16(b0 + KVB + so,     klo + gk);
            cpa16(b0 + 2 * KVB + so, vhi + gk);
            cpa16(b0 + 3 * KVB + so, vlo + gk);
        }
    };

    float m0 = -1e30f, m1 = -1e30f, l0 = 0.0f, l1 = 0.0f;
    float out[8][4] = {};

    issue(0, 0);
    CPA_COMMIT();

    for (int tile = 0; tile < 16; tile++) {
        if (tile < 15) { issue((tile + 1) * 128, (tile + 1) & 1); CPA_COMMIT(); CPA_WAIT1(); }
        else CPA_WAIT0();
        __syncthreads();

        uint32_t kb = sb + (tile & 1) * STAGEB;
        uint32_t vb = kb + 2 * KVB;

        // QK^T -> s[16][4]
        float s[16][4] = {};
#pragma unroll
        for (int ks = 0; ks < 4; ks++) {
#pragma unroll
            for (int nfp = 0; nfp < 8; nfp++) {
                uint32_t ad = kb +
                    (uint32_t)(((nfp * 2 + (lm >> 1)) * 8 + li) * PKV
                               + ks * 16 + (lm & 1) * 8) * 2;
                uint32_t bhv[4], blv[4];
                ldsm_x4(bhv, ad);
                ldsm_x4(blv, ad + KVB);
                mma16816(s[nfp*2],   qh[ks], bhv);
                mma16816(s[nfp*2],   qh[ks], blv);
                mma16816(s[nfp*2],   ql[ks], bhv);
                mma16816(s[nfp*2+1], qh[ks], bhv + 2);
                mma16816(s[nfp*2+1], qh[ks], blv + 2);
                mma16816(s[nfp*2+1], ql[ks], bhv + 2);
            }
        }

        // warp-local online softmax (scale 0.125 folded into exp)
        float mx0 = -1e30f, mx1 = -1e30f;
#pragma unroll
        for (int nf = 0; nf < 16; nf++) {
            mx0 = fmaxf(mx0, fmaxf(s[nf][0], s[nf][1]));
            mx1 = fmaxf(mx1, fmaxf(s[nf][2], s[nf][3]));
        }
        mx0 = fmaxf(mx0, __shfl_xor_sync(0xffffffffu, mx0, 1));
        mx0 = fmaxf(mx0, __shfl_xor_sync(0xffffffffu, mx0, 2));
        mx1 = fmaxf(mx1, __shfl_xor_sync(0xffffffffu, mx1, 1));
        mx1 = fmaxf(mx1, __shfl_xor_sync(0xffffffffu, mx1, 2));
        float mn0 = fmaxf(m0, mx0), mn1 = fmaxf(m1, mx1);
        float sc0 = __expf(0.125f * (m0 - mn0));
        float sc1 = __expf(0.125f * (m1 - mn1));
        float sum0 = 0.0f, sum1 = 0.0f;
#pragma unroll
        for (int nf = 0; nf < 16; nf++) {
            s[nf][0] = __expf(0.125f * (s[nf][0] - mn0));
            s[nf][1] = __expf(0.125f * (s[nf][1] - mn0));
            s[nf][2] = __expf(0.125f * (s[nf][2] - mn1));
            s[nf][3] = __expf(0.125f * (s[nf][3] - mn1));
            sum0 += s[nf][0] + s[nf][1];
            sum1 += s[nf][2] + s[nf][3];
        }
        sum0 += __shfl_xor_sync(0xffffffffu, sum0, 1);
        sum0 += __shfl_xor_sync(0xffffffffu, sum0, 2);
        sum1 += __shfl_xor_sync(0xffffffffu, sum1, 1);
        sum1 += __shfl_xor_sync(0xffffffffu, sum1, 2);
        l0 = l0 * sc0 + sum0;
        l1 = l1 * sc1 + sum1;
        m0 = mn0; m1 = mn1;
#pragma unroll
        for (int nfo = 0; nfo < 8; nfo++) {
            out[nfo][0] *= sc0; out[nfo][1] *= sc0;
            out[nfo][2] *= sc1; out[nfo][3] *= sc1;
        }

        // PV: O += P @ V   (A = P regs split hi/lo, B via ldmatrix.trans)
#pragma unroll
        for (int ks2 = 0; ks2 < 8; ks2++) {
            uint32_t ah[4], al[4];
            ah[0] = pack_hi(s[2*ks2][0],   s[2*ks2][1]);
            ah[1] = pack_hi(s[2*ks2][2],   s[2*ks2][3]);
            ah[2] = pack_hi(s[2*ks2+1][0], s[2*ks2+1][1]);
            ah[3] = pack_hi(s[2*ks2+1][2], s[2*ks2+1][3]);
            al[0] = pack_lo(s[2*ks2][0],   s[2*ks2][1],   ah[0]);
            al[1] = pack_lo(s[2*ks2][2],   s[2*ks2][3],   ah[1]);
            al[2] = pack_lo(s[2*ks2+1][0], s[2*ks2+1][1], ah[2]);
            al[3] = pack_lo(s[2*ks2+1][2], s[2*ks2+1][3], ah[3]);
#pragma unroll
            for (int nfp = 0; nfp < 4; nfp++) {
                uint32_t ad = vb +
                    (uint32_t)((ks2 * 16 + (lm & 1) * 8 + li) * PKV
                               + (nfp * 2 + (lm >> 1)) * 8) * 2;
                uint32_t bvh[4], bvl[4];
                ldsm_x4_t(bvh, ad);
                ldsm_x4_t(bvl, ad + KVB);
                mma16816(out[nfp*2],   ah, bvh);
                mma16816(out[nfp*2],   ah, bvl);
                mma16816(out[nfp*2],   al, bvh);
                mma16816(out[nfp*2+1], ah, bvh + 2);
                mma16816(out[nfp*2+1], ah, bvl + 2);
                mma16816(out[nfp*2+1], al, bvh + 2);
            }
        }
        __syncthreads();
    }

    // normalize + write ctx hi/lo
    float inv0 = 1.0f / l0, inv1 = 1.0f / l1;
    size_t r0 = base + (size_t)(q0 + wid * 16 + g) * Ee;
    size_t r1 = r0 + 8 * (size_t)Ee;
#pragma unroll
    for (int nfo = 0; nfo < 8; nfo++) {
        int d = nfo * 8 + 2 * t;
        float v0 = out[nfo][0] * inv0, v1 = out[nfo][1] * inv0;
        float v2 = out[nfo][2] * inv1, v3 = out[nfo][3] * inv1;
        uint32_t h0 = pack_hi(v0, v1), h1 = pack_hi(v2, v3);
        *(uint32_t*)&chi[r0 + d] = h0;
        *(uint32_t*)&chi[r1 + d] = h1;
        *(uint32_t*)&clo[r0 + d] = pack_lo(v0, v1, h0);
        *(uint32_t*)&clo[r1 + d] = pack_lo(v2, v3, h1);
    }
}

// ---------------------------------------------------------------------------
extern "C" void kernel_launch(void* const* d_in, const int* in_sizes, int n_in,
                              void* d_out, int out_size)
{
    const float* x     = (const float*)d_in[0];
    const float* Wq    = (const float*)d_in[1];
    const float* Wk    = (const float*)d_in[2];
    const float* Wv    = (const float*)d_in[3];
    const float* Wo    = (const float*)d_in[4];
    const float* theta = (const float*)d_in[5];
    float* out = (float*)d_out;

    __nv_bfloat16 *xhi, *xlo, *qhi, *qlo, *khi, *klo, *vhi, *vlo,
                  *chi, *clo, *whi, *wlo;
    cudaGetSymbolAddress((void**)&xhi, g_xhi);
    cudaGetSymbolAddress((void**)&xlo, g_xlo);
    cudaGetSymbolAddress((void**)&qhi, g_qhi);
    cudaGetSymbolAddress((void**)&qlo, g_qlo);
    cudaGetSymbolAddress((void**)&khi, g_khi);
    cudaGetSymbolAddress((void**)&klo, g_klo);
    cudaGetSymbolAddress((void**)&vhi, g_vhi);
    cudaGetSymbolAddress((void**)&vlo, g_vlo);
    cudaGetSymbolAddress((void**)&chi, g_chi);
    cudaGetSymbolAddress((void**)&clo, g_clo);
    cudaGetSymbolAddress((void**)&whi, g_whi);
    cudaGetSymbolAddress((void**)&wlo, g_wlo);

    cudaFuncSetAttribute(hmma_gemm<true>,
        cudaFuncAttributeMaxDynamicSharedMemorySize, GEMM_SMEM);
    cudaFuncSetAttribute(hmma_gemm<false>,
        cudaFuncAttributeMaxDynamicSharedMemorySize, GEMM_SMEM);
    cudaFuncSetAttribute(attn_mma,
        cudaFuncAttributeMaxDynamicSharedMemorySize, ATT_SMEM);

    int n4x = Mm * Ee / 4;
    int n4w = Ee * Ee / 4;
    split_kernel<<<(n4x + 255) / 256, 256>>>((const float4*)x,  xhi, xlo, n4x);
    split_kernel<<<(n4w + 255) / 256, 256>>>((const float4*)Wq, whi + 0*(size_t)Ee*Ee, wlo + 0*(size_t)Ee*Ee, n4w);
    split_kernel<<<(n4w + 255) / 256, 256>>>((const float4*)Wk, whi + 1*(size_t)Ee*Ee, wlo + 1*(size_t)Ee*Ee, n4w);
    split_kernel<<<(n4w + 255) / 256, 256>>>((const float4*)Wv, whi + 2*(size_t)Ee*Ee, wlo + 2*(size_t)Ee*Ee, n4w);
    split_kernel<<<(n4w + 255) / 256, 256>>>((const float4*)Wo, whi + 3*(size_t)Ee*Ee, wlo + 3*(size_t)Ee*Ee, n4w);

    dim3 blk(256);
    dim3 g1(Ee / 128, Mm / 128);   // (8, 64)
    hmma_gemm<true><<<g1, blk, GEMM_SMEM>>>(xhi, xlo,
        whi + 0*(size_t)Ee*Ee, wlo + 0*(size_t)Ee*Ee, theta, nullptr, qhi, qlo);
    hmma_gemm<true><<<g1, blk, GEMM_SMEM>>>(xhi, xlo,
        whi + 1*(size_t)Ee*Ee, wlo + 1*(size_t)Ee*Ee, theta, nullptr, khi, klo);
    hmma_gemm<true><<<g1, blk, GEMM_SMEM>>>(xhi, xlo,
        whi + 2*(size_t)Ee*Ee, wlo + 2*(size_t)Ee*Ee, theta, nullptr, vhi, vlo);

    dim3 g2(Ss / 128, Bb * Hh);    // (16, 64)
    attn_mma<<<g2, blk, ATT_SMEM>>>(qhi, qlo, khi, klo, vhi, vlo, chi, clo);

    hmma_gemm<false><<<g1, blk, GEMM_SMEM>>>(chi, clo,
        whi + 3*(size_t)Ee*Ee, wlo + 3*(size_t)Ee*Ee, nullptr, out, nullptr, nullptr);
}

// round 6
// speedup vs baseline: 3.7521x; 1.1773x over previous
#include <cuda_runtime.h>
#include <cuda_bf16.h>
#include <math.h>
#include <stdint.h>

#define Bb 4
#define Ss 2048
#define Ee 1024
#define Hh 16
#define Dk 64
#define Mm (Bb*Ss)   /* 8192 */

// ------------------------- device scratch (no allocs) ----------------------
__device__ __nv_bfloat16 g_xhi[Mm*Ee];
__device__ __nv_bfloat16 g_xlo[Mm*Ee];
__device__ __nv_bfloat16 g_qkvhi[3*Mm*Ee];   // q | k | v
__device__ __nv_bfloat16 g_qkvlo[3*Mm*Ee];
__device__ __nv_bfloat16 g_chi[Mm*Ee];
__device__ __nv_bfloat16 g_clo[Mm*Ee];
__device__ __nv_bfloat16 g_whi[4*Ee*Ee];
__device__ __nv_bfloat16 g_wlo[4*Ee*Ee];

// ------------------------- helpers ------------------------------------------
__device__ __forceinline__ void mma16816(float* d, const uint32_t* a,
                                         const uint32_t* b)
{
    asm volatile(
        "mma.sync.aligned.m16n8k16.row.col.f32.bf16.bf16.f32 "
        "{%0,%1,%2,%3}, {%4,%5,%6,%7}, {%8,%9}, {%0,%1,%2,%3};"
        : "+f"(d[0]), "+f"(d[1]), "+f"(d[2]), "+f"(d[3])
        : "r"(a[0]), "r"(a[1]), "r"(a[2]), "r"(a[3]), "r"(b[0]), "r"(b[1]));
}
__device__ __forceinline__ void ldsm_x4(uint32_t* r, uint32_t addr) {
    asm volatile("ldmatrix.sync.aligned.m8n8.x4.shared.b16 {%0,%1,%2,%3}, [%4];"
        : "=r"(r[0]), "=r"(r[1]), "=r"(r[2]), "=r"(r[3]) : "r"(addr));
}
__device__ __forceinline__ void ldsm_x4_t(uint32_t* r, uint32_t addr) {
    asm volatile("ldmatrix.sync.aligned.m8n8.x4.trans.shared.b16 {%0,%1,%2,%3}, [%4];"
        : "=r"(r[0]), "=r"(r[1]), "=r"(r[2]), "=r"(r[3]) : "r"(addr));
}
__device__ __forceinline__ uint32_t smem_u32(const void* p) {
    uint32_t a;
    asm("{ .reg .u64 t; cvta.to.shared.u64 t, %1; cvt.u32.u64 %0, t; }"
        : "=r"(a) : "l"(p));
    return a;
}
__device__ __forceinline__ void cpa16(uint32_t s, const void* g) {
    asm volatile("cp.async.cg.shared.global [%0], [%1], 16;" :: "r"(s), "l"(g));
}
#define CPA_COMMIT() asm volatile("cp.async.commit_group;" ::: "memory")
#define CPA_WAIT1()  asm volatile("cp.async.wait_group 1;" ::: "memory")
#define CPA_WAIT0()  asm volatile("cp.async.wait_group 0;" ::: "memory")

__device__ __forceinline__ uint32_t pack_hi(float x, float y) {
    __nv_bfloat162 h = __floats2bfloat162_rn(x, y);
    return *(uint32_t*)&h;
}
__device__ __forceinline__ uint32_t pack_lo(float x, float y, uint32_t hiu) {
    __nv_bfloat162 h = *(__nv_bfloat162*)&hiu;
    __nv_bfloat162 l = __floats2bfloat162_rn(x - __bfloat162float(h.x),
                                             y - __bfloat162float(h.y));
    return *(uint32_t*)&l;
}
// unpack packed bf16x2 halves to f32
__device__ __forceinline__ float unp_lo(uint32_t u) {
    return __uint_as_float(u << 16);
}
__device__ __forceinline__ float unp_hi(uint32_t u) {
    return __uint_as_float(u & 0xffff0000u);
}

// ------------------------- fp32 -> bf16 hi/lo split --------------------------
__global__ __launch_bounds__(256) void split_kernel(const float4* __restrict__ src,
                                                    __nv_bfloat16* __restrict__ hi,
                                                    __nv_bfloat16* __restrict__ lo,
                                                    int n4)
{
    int i = blockIdx.x * 256 + threadIdx.x;
    if (i >= n4) return;
    float4 v = src[i];
    uint32_t h0 = pack_hi(v.x, v.y), h1 = pack_hi(v.z, v.w);
    uint32_t l0 = pack_lo(v.x, v.y, h0), l1 = pack_lo(v.z, v.w, h1);
    uint32_t* hp = (uint32_t*)(hi + (size_t)i * 4);
    uint32_t* lp = (uint32_t*)(lo + (size_t)i * 4);
    hp[0] = h0; hp[1] = h1; lp[0] = l0; lp[1] = l1;
}

// ------------------------- HMMA split-bf16 GEMM (3-stage cp.async) -----------
// z = blockIdx.z selects weight matrix / output. DO_COS -> bf16 hi/lo outputs.
#define PCH 72
#define TILE_B (128 * PCH * 2)            /* 18432 bytes per array */
#define GSTAGE (TILE_B * 4)               /* 73728 */
#define GEMM_SMEM (GSTAGE * 3)            /* 221184 */

template<bool DO_COS>
__global__ __launch_bounds__(256, 1) void hmma_gemm(
    const __nv_bfloat16* __restrict__ Ahi, const __nv_bfloat16* __restrict__ Alo,
    const __nv_bfloat16* __restrict__ WhiB, const __nv_bfloat16* __restrict__ WloB,
    const float* __restrict__ theta,
    float* __restrict__ C,
    __nv_bfloat16* __restrict__ OHB, __nv_bfloat16* __restrict__ OLB)
{
    extern __shared__ __align__(16) char smem[];
    uint32_t sb = smem_u32(smem);

    int z = blockIdx.z;
    const __nv_bfloat16* Whi = WhiB + (size_t)z * Ee * Ee;
    const __nv_bfloat16* Wlo = WloB + (size_t)z * Ee * Ee;

    int tid = threadIdx.x, wid = tid >> 5, lane = tid & 31;
    int wm = wid & 1, wn = wid >> 1;
    int g = lane >> 2, t = lane & 3;
    int lm = lane >> 3, li = lane & 7;
    int m0 = blockIdx.y * 128, n0 = blockIdx.x * 128;

    float acc[4][4][4] = {};

    auto issue = [&](int c, int bs) {
        uint32_t b0 = sb + bs * GSTAGE;
#pragma unroll
        for (int u = 0; u < 4; u++) {
            int unit = tid + u * 256;
            int row = unit >> 3, seg = unit & 7;
            size_t gA = (size_t)(m0 + row) * Ee + c * 64 + seg * 8;
            size_t gW = (size_t)(n0 + row) * Ee + c * 64 + seg * 8;
            uint32_t so = (uint32_t)(row * PCH + seg * 8) * 2;
            cpa16(b0 + so,              Ahi + gA);
            cpa16(b0 + TILE_B + so,     Alo + gA);
            cpa16(b0 + 2 * TILE_B + so, Whi + gW);
            cpa16(b0 + 3 * TILE_B + so, Wlo + gW);
        }
    };

    issue(0, 0); CPA_COMMIT();
    issue(1, 1); CPA_COMMIT();

    for (int c = 0; c < 16; c++) {
        if (c == 15) CPA_WAIT0(); else CPA_WAIT1();
        __syncthreads();
        if (c < 14) { issue(c + 2, (c + 2) % 3); CPA_COMMIT(); }

        uint32_t bufA = sb + (c % 3) * GSTAGE;
        uint32_t bufW = bufA + 2 * TILE_B;

#pragma unroll
        for (int ks = 0; ks < 4; ks++) {
            uint32_t ah[4][4], al[4][4];
#pragma unroll
            for (int mf = 0; mf < 4; mf++) {
                uint32_t ad = bufA +
                    (uint32_t)(((wm * 64 + mf * 16 + (lm & 1) * 8 + li) * PCH)
                               + ks * 16 + (lm >> 1) * 8) * 2;
                ldsm_x4(ah[mf], ad);
                ldsm_x4(al[mf], ad + TILE_B);
            }
#pragma unroll
            for (int nfp = 0; nfp < 2; nfp++) {
                uint32_t bd = bufW +
                    (uint32_t)(((wn * 32 + (nfp * 2 + (lm >> 1)) * 8 + li) * PCH)
                               + ks * 16 + (lm & 1) * 8) * 2;
                uint32_t bh[4], bl[4];
                ldsm_x4(bh, bd);
                ldsm_x4(bl, bd + TILE_B);
#pragma unroll
                for (int mf = 0; mf < 4; mf++) {
                    mma16816(acc[mf][nfp*2],   ah[mf], bh);
                    mma16816(acc[mf][nfp*2],   ah[mf], bl);
                    mma16816(acc[mf][nfp*2],   al[mf], bh);
                    mma16816(acc[mf][nfp*2+1], ah[mf], bh + 2);
                    mma16816(acc[mf][nfp*2+1], ah[mf], bl + 2);
                    mma16816(acc[mf][nfp*2+1], al[mf], bh + 2);
                }
            }
        }
    }

    // epilogue
    __nv_bfloat16* OH = DO_COS ? OHB + (size_t)z * Mm * Ee : nullptr;
    __nv_bfloat16* OL = DO_COS ? OLB + (size_t)z * Mm * Ee : nullptr;
#pragma unroll
    for (int mf = 0; mf < 4; mf++) {
#pragma unroll
        for (int nf = 0; nf < 4; nf++) {
            int r = m0 + wm * 64 + mf * 16 + g;
            int cb = n0 + wn * 32 + nf * 8 + 2 * t;
            float v0 = acc[mf][nf][0], v1 = acc[mf][nf][1];
            float v2 = acc[mf][nf][2], v3 = acc[mf][nf][3];
            if (DO_COS) {
                float t0 = theta[cb & 63], t1 = theta[(cb + 1) & 63];
                v0 = cosf(v0 + t0); v1 = cosf(v1 + t1);
                v2 = cosf(v2 + t0); v3 = cosf(v3 + t1);
                uint32_t h0 = pack_hi(v0, v1), h1 = pack_hi(v2, v3);
                *(uint32_t*)&OH[(size_t)r * Ee + cb]       = h0;
                *(uint32_t*)&OH[(size_t)(r + 8) * Ee + cb] = h1;
                *(uint32_t*)&OL[(size_t)r * Ee + cb]       = pack_lo(v0, v1, h0);
                *(uint32_t*)&OL[(size_t)(r + 8) * Ee + cb] = pack_lo(v2, v3, h1);
            } else {
                *(float2*)&C[(size_t)r * Ee + cb]       = float2{v0, v1};
                *(float2*)&C[(size_t)(r + 8) * Ee + cb] = float2{v2, v3};
            }
        }
    }
}

// ------------------------- HMMA flash attention (3-stage, reduced split) -----
// Per stage: Kh | Kl | Vh | Vl, each 128 rows x 64 d, pitch 72 bf16.
#define PKV 72
#define KVB (128 * PKV * 2)              /* 18432 */
#define STAGEB (KVB * 4)                 /* 73728 */
#define ATT_SMEM (STAGEB * 3)            /* 221184 */

__global__ __launch_bounds__(256, 1) void attn_mma(
    const __nv_bfloat16* __restrict__ qhi,
    const __nv_bfloat16* __restrict__ khi, const __nv_bfloat16* __restrict__ klo,
    const __nv_bfloat16* __restrict__ vhi, const __nv_bfloat16* __restrict__ vlo,
    __nv_bfloat16* __restrict__ chi, __nv_bfloat16* __restrict__ clo)
{
    extern __shared__ __align__(16) char smem[];
    uint32_t sb = smem_u32(smem);

    int tid = threadIdx.x, wid = tid >> 5, lane = tid & 31;
    int g = lane >> 2, t = lane & 3;
    int lm = lane >> 3, li = lane & 7;
    int bh_ = blockIdx.y;
    int b = bh_ >> 4, h = bh_ & 15;
    int q0 = blockIdx.x * 128;
    size_t base = (size_t)b * Ss * Ee + (size_t)h * Dk;

    // Q hi fragments only (2-term QK^T), 4 k-steps
    uint32_t qh[4][4];
    {
        size_t r0 = base + (size_t)(q0 + wid * 16 + g) * Ee;
        size_t r1 = r0 + 8 * (size_t)Ee;
#pragma unroll
        for (int ks = 0; ks < 4; ks++) {
            int c0 = ks * 16 + 2 * t;
            qh[ks][0] = *(const uint32_t*)&qhi[r0 + c0];
            qh[ks][1] = *(const uint32_t*)&qhi[r1 + c0];
            qh[ks][2] = *(const uint32_t*)&qhi[r0 + c0 + 8];
            qh[ks][3] = *(const uint32_t*)&qhi[r1 + c0 + 8];
        }
    }

    auto issue = [&](int j0, int s) {
        uint32_t b0 = sb + s * STAGEB;
#pragma unroll
        for (int u = 0; u < 4; u++) {
            int unit = tid + u * 256;
            int row = unit >> 3, seg = unit & 7;
            size_t gk = base + (size_t)(j0 + row) * Ee + seg * 8;
            uint32_t so = (uint32_t)(row * PKV + seg * 8) * 2;
            cpa16(b0 + so,           khi + gk);
            cpa16(b0 + KVB + so,     klo + gk);
            cpa16(b0 + 2 * KVB + so, vhi + gk);
            cpa16(b0 + 3 * KVB + so, vlo + gk);
        }
    };

    float m0 = -1e30f, m1 = -1e30f, l0 = 0.0f, l1 = 0.0f;
    float out[8][4] = {};

    issue(0, 0);   CPA_COMMIT();
    issue(128, 1); CPA_COMMIT();

    for (int tile = 0; tile < 16; tile++) {
        if (tile == 15) CPA_WAIT0(); else CPA_WAIT1();
        __syncthreads();
        if (tile < 14) { issue((tile + 2) * 128, (tile + 2) % 3); CPA_COMMIT(); }

        uint32_t kb = sb + (tile % 3) * STAGEB;
        uint32_t vb = kb + 2 * KVB;

        // QK^T (2-term: qh*kh + qh*kl) -> s[16][4]
        float s[16][4] = {};
#pragma unroll
        for (int ks = 0; ks < 4; ks++) {
#pragma unroll
            for (int nfp = 0; nfp < 8; nfp++) {
                uint32_t ad = kb +
                    (uint32_t)(((nfp * 2 + (lm >> 1)) * 8 + li) * PKV
                               + ks * 16 + (lm & 1) * 8) * 2;
                uint32_t bhv[4], blv[4];
                ldsm_x4(bhv, ad);
                ldsm_x4(blv, ad + KVB);
                mma16816(s[nfp*2],   qh[ks], bhv);
                mma16816(s[nfp*2],   qh[ks], blv);
                mma16816(s[nfp*2+1], qh[ks], bhv + 2);
                mma16816(s[nfp*2+1], qh[ks], blv + 2);
            }
        }

        // warp-local online softmax (scale 0.125 folded into exp)
        float mx0 = -1e30f, mx1 = -1e30f;
#pragma unroll
        for (int nf = 0; nf < 16; nf++) {
            mx0 = fmaxf(mx0, fmaxf(s[nf][0], s[nf][1]));
            mx1 = fmaxf(mx1, fmaxf(s[nf][2], s[nf][3]));
        }
        mx0 = fmaxf(mx0, __shfl_xor_sync(0xffffffffu, mx0, 1));
        mx0 = fmaxf(mx0, __shfl_xor_sync(0xffffffffu, mx0, 2));
        mx1 = fmaxf(mx1, __shfl_xor_sync(0xffffffffu, mx1, 1));
        mx1 = fmaxf(mx1, __shfl_xor_sync(0xffffffffu, mx1, 2));
        float mn0 = fmaxf(m0, mx0), mn1 = fmaxf(m1, mx1);
        float sc0 = __expf(0.125f * (m0 - mn0));
        float sc1 = __expf(0.125f * (m1 - mn1));
#pragma unroll
        for (int nf = 0; nf < 16; nf++) {
            s[nf][0] = __expf(0.125f * (s[nf][0] - mn0));
            s[nf][1] = __expf(0.125f * (s[nf][1] - mn0));
            s[nf][2] = __expf(0.125f * (s[nf][2] - mn1));
            s[nf][3] = __expf(0.125f * (s[nf][3] - mn1));
        }

        // pack P to bf16 (hi only); sum the ROUNDED values so the
        // normalizer exactly matches the weights used in the PV MMAs.
        uint32_t pa[8][4];
        float sum0 = 0.0f, sum1 = 0.0f;
#pragma unroll
        for (int k2 = 0; k2 < 8; k2++) {
            pa[k2][0] = pack_hi(s[2*k2][0],   s[2*k2][1]);
            pa[k2][1] = pack_hi(s[2*k2][2],   s[2*k2][3]);
            pa[k2][2] = pack_hi(s[2*k2+1][0], s[2*k2+1][1]);
            pa[k2][3] = pack_hi(s[2*k2+1][2], s[2*k2+1][3]);
            sum0 += unp_lo(pa[k2][0]) + unp_hi(pa[k2][0])
                  + unp_lo(pa[k2][2]) + unp_hi(pa[k2][2]);
            sum1 += unp_lo(pa[k2][1]) + unp_hi(pa[k2][1])
                  + unp_lo(pa[k2][3]) + unp_hi(pa[k2][3]);
        }
        sum0 += __shfl_xor_sync(0xffffffffu, sum0, 1);
        sum0 += __shfl_xor_sync(0xffffffffu, sum0, 2);
        sum1 += __shfl_xor_sync(0xffffffffu, sum1, 1);
        sum1 += __shfl_xor_sync(0xffffffffu, sum1, 2);
        l0 = l0 * sc0 + sum0;
        l1 = l1 * sc1 + sum1;
        m0 = mn0; m1 = mn1;
#pragma unroll
        for (int nfo = 0; nfo < 8; nfo++) {
            out[nfo][0] *= sc0; out[nfo][1] *= sc0;
            out[nfo][2] *= sc1; out[nfo][3] *= sc1;
        }

        // PV (2-term: p_hat * (vh + vl)), B via ldmatrix.trans
#pragma unroll
        for (int ks2 = 0; ks2 < 8; ks2++) {
#pragma unroll
            for (int nfp = 0; nfp < 4; nfp++) {
                uint32_t ad = vb +
                    (uint32_t)((ks2 * 16 + (lm & 1) * 8 + li) * PKV
                               + (nfp * 2 + (lm >> 1)) * 8) * 2;
                uint32_t bvh[4], bvl[4];
                ldsm_x4_t(bvh, ad);
                ldsm_x4_t(bvl, ad + KVB);
                mma16816(out[nfp*2],   pa[ks2], bvh);
                mma16816(out[nfp*2],   pa[ks2], bvl);
                mma16816(out[nfp*2+1], pa[ks2], bvh + 2);
                mma16816(out[nfp*2+1], pa[ks2], bvl + 2);
            }
        }
    }

    // normalize + write ctx hi/lo
    float inv0 = 1.0f / l0, inv1 = 1.0f / l1;
    size_t r0 = base + (size_t)(q0 + wid * 16 + g) * Ee;
    size_t r1 = r0 + 8 * (size_t)Ee;
#pragma unroll
    for (int nfo = 0; nfo < 8; nfo++) {
        int d = nfo * 8 + 2 * t;
        float v0 = out[nfo][0] * inv0, v1 = out[nfo][1] * inv0;
        float v2 = out[nfo][2] * inv1, v3 = out[nfo][3] * inv1;
        uint32_t h0 = pack_hi(v0, v1), h1 = pack_hi(v2, v3);
        *(uint32_t*)&chi[r0 + d] = h0;
        *(uint32_t*)&chi[r1 + d] = h1;
        *(uint32_t*)&clo[r0 + d] = pack_lo(v0, v1, h0);
        *(uint32_t*)&clo[r1 + d] = pack_lo(v2, v3, h1);
    }
}

// ---------------------------------------------------------------------------
extern "C" void kernel_launch(void* const* d_in, const int* in_sizes, int n_in,
                              void* d_out, int out_size)
{
    const float* x     = (const float*)d_in[0];
    const float* Wq    = (const float*)d_in[1];
    const float* Wk    = (const float*)d_in[2];
    const float* Wv    = (const float*)d_in[3];
    const float* Wo    = (const float*)d_in[4];
    const float* theta = (const float*)d_in[5];
    float* out = (float*)d_out;

    __nv_bfloat16 *xhi, *xlo, *qkvhi, *qkvlo, *chi, *clo, *whi, *wlo;
    cudaGetSymbolAddress((void**)&xhi, g_xhi);
    cudaGetSymbolAddress((void**)&xlo, g_xlo);
    cudaGetSymbolAddress((void**)&qkvhi, g_qkvhi);
    cudaGetSymbolAddress((void**)&qkvlo, g_qkvlo);
    cudaGetSymbolAddress((void**)&chi, g_chi);
    cudaGetSymbolAddress((void**)&clo, g_clo);
    cudaGetSymbolAddress((void**)&whi, g_whi);
    cudaGetSymbolAddress((void**)&wlo, g_wlo);

    cudaFuncSetAttribute(hmma_gemm<true>,
        cudaFuncAttributeMaxDynamicSharedMemorySize, GEMM_SMEM);
    cudaFuncSetAttribute(hmma_gemm<false>,
        cudaFuncAttributeMaxDynamicSharedMemorySize, GEMM_SMEM);
    cudaFuncSetAttribute(attn_mma,
        cudaFuncAttributeMaxDynamicSharedMemorySize, ATT_SMEM);

    int n4x = Mm * Ee / 4;
    int n4w = Ee * Ee / 4;
    split_kernel<<<(n4x + 255) / 256, 256>>>((const float4*)x,  xhi, xlo, n4x);
    split_kernel<<<(n4w + 255) / 256, 256>>>((const float4*)Wq, whi + 0*(size_t)Ee*Ee, wlo + 0*(size_t)Ee*Ee, n4w);
    split_kernel<<<(n4w + 255) / 256, 256>>>((const float4*)Wk, whi + 1*(size_t)Ee*Ee, wlo + 1*(size_t)Ee*Ee, n4w);
    split_kernel<<<(n4w + 255) / 256, 256>>>((const float4*)Wv, whi + 2*(size_t)Ee*Ee, wlo + 2*(size_t)Ee*Ee, n4w);
    split_kernel<<<(n4w + 255) / 256, 256>>>((const float4*)Wo, whi + 3*(size_t)Ee*Ee, wlo + 3*(size_t)Ee*Ee, n4w);

    dim3 blk(256);
    dim3 g1(Ee / 128, Mm / 128, 3);   // fused Q/K/V projections
    hmma_gemm<true><<<g1, blk, GEMM_SMEM>>>(xhi, xlo, whi, wlo, theta,
                                            nullptr, qkvhi, qkvlo);

    size_t off = (size_t)Mm * Ee;
    dim3 g2(Ss / 128, Bb * Hh);       // (16, 64)
    attn_mma<<<g2, blk, ATT_SMEM>>>(qkvhi,                    // q hi
                                    qkvhi + off, qkvlo + off, // k hi/lo
                                    qkvhi + 2*off, qkvlo + 2*off, // v hi/lo
                                    chi, clo);

    dim3 g3(Ee / 128, Mm / 128, 1);
    hmma_gemm<false><<<g3, blk, GEMM_SMEM>>>(chi, clo,
        whi + 3*(size_t)Ee*Ee, wlo + 3*(size_t)Ee*Ee, nullptr, out,
        nullptr, nullptr);
}

// round 7
// speedup vs baseline: 3.8556x; 1.0276x over previous
#include <cuda_runtime.h>
#include <cuda_bf16.h>
#include <math.h>
#include <stdint.h>

#define Bb 4
#define Ss 2048
#define Ee 1024
#define Hh 16
#define Dk 64
#define Mm (Bb*Ss)   /* 8192 */

// ------------------------- device scratch (no allocs) ----------------------
__device__ __nv_bfloat16 g_xhi[Mm*Ee];
__device__ __nv_bfloat16 g_xlo[Mm*Ee];
__device__ __nv_bfloat16 g_qkvhi[3*Mm*Ee];   // q | k | v
__device__ __nv_bfloat16 g_qkvlo[3*Mm*Ee];
__device__ __nv_bfloat16 g_chi[Mm*Ee];
__device__ __nv_bfloat16 g_clo[Mm*Ee];
__device__ __nv_bfloat16 g_whi[4*Ee*Ee];
__device__ __nv_bfloat16 g_wlo[4*Ee*Ee];

// ------------------------- helpers ------------------------------------------
__device__ __forceinline__ void mma16816(float* d, const uint32_t* a,
                                         const uint32_t* b)
{
    asm volatile(
        "mma.sync.aligned.m16n8k16.row.col.f32.bf16.bf16.f32 "
        "{%0,%1,%2,%3}, {%4,%5,%6,%7}, {%8,%9}, {%0,%1,%2,%3};"
        : "+f"(d[0]), "+f"(d[1]), "+f"(d[2]), "+f"(d[3])
        : "r"(a[0]), "r"(a[1]), "r"(a[2]), "r"(a[3]), "r"(b[0]), "r"(b[1]));
}
__device__ __forceinline__ void ldsm_x4(uint32_t* r, uint32_t addr) {
    asm volatile("ldmatrix.sync.aligned.m8n8.x4.shared.b16 {%0,%1,%2,%3}, [%4];"
        : "=r"(r[0]), "=r"(r[1]), "=r"(r[2]), "=r"(r[3]) : "r"(addr));
}
__device__ __forceinline__ void ldsm_x4_t(uint32_t* r, uint32_t addr) {
    asm volatile("ldmatrix.sync.aligned.m8n8.x4.trans.shared.b16 {%0,%1,%2,%3}, [%4];"
        : "=r"(r[0]), "=r"(r[1]), "=r"(r[2]), "=r"(r[3]) : "r"(addr));
}
__device__ __forceinline__ uint32_t smem_u32(const void* p) {
    uint32_t a;
    asm("{ .reg .u64 t; cvta.to.shared.u64 t, %1; cvt.u32.u64 %0, t; }"
        : "=r"(a) : "l"(p));
    return a;
}
__device__ __forceinline__ void cpa16(uint32_t s, const void* g) {
    asm volatile("cp.async.cg.shared.global [%0], [%1], 16;" :: "r"(s), "l"(g));
}
#define CPA_COMMIT() asm volatile("cp.async.commit_group;" ::: "memory")
#define CPA_WAIT1()  asm volatile("cp.async.wait_group 1;" ::: "memory")
#define CPA_WAIT0()  asm volatile("cp.async.wait_group 0;" ::: "memory")

__device__ __forceinline__ uint32_t pack_hi(float x, float y) {
    __nv_bfloat162 h = __floats2bfloat162_rn(x, y);
    return *(uint32_t*)&h;
}
__device__ __forceinline__ uint32_t pack_lo(float x, float y, uint32_t hiu) {
    __nv_bfloat162 h = *(__nv_bfloat162*)&hiu;
    __nv_bfloat162 l = __floats2bfloat162_rn(x - __bfloat162float(h.x),
                                             y - __bfloat162float(h.y));
    return *(uint32_t*)&l;
}
__device__ __forceinline__ float unp_lo(uint32_t u) {
    return __uint_as_float(u << 16);
}
__device__ __forceinline__ float unp_hi(uint32_t u) {
    return __uint_as_float(u & 0xffff0000u);
}

// ------------------------- fp32 -> bf16 hi/lo splits -------------------------
__global__ __launch_bounds__(256) void split_kernel(const float4* __restrict__ src,
                                                    __nv_bfloat16* __restrict__ hi,
                                                    __nv_bfloat16* __restrict__ lo,
                                                    int n4)
{
    int i = blockIdx.x * 256 + threadIdx.x;
    if (i >= n4) return;
    float4 v = src[i];
    uint32_t h0 = pack_hi(v.x, v.y), h1 = pack_hi(v.z, v.w);
    uint32_t l0 = pack_lo(v.x, v.y, h0), l1 = pack_lo(v.z, v.w, h1);
    uint32_t* hp = (uint32_t*)(hi + (size_t)i * 4);
    uint32_t* lp = (uint32_t*)(lo + (size_t)i * 4);
    hp[0] = h0; hp[1] = h1; lp[0] = l0; lp[1] = l1;
}

// fused 4-weight split: blockIdx.y selects source matrix
__global__ __launch_bounds__(256) void split4_kernel(
    const float4* __restrict__ s0, const float4* __restrict__ s1,
    const float4* __restrict__ s2, const float4* __restrict__ s3,
    __nv_bfloat16* __restrict__ hi, __nv_bfloat16* __restrict__ lo, int n4)
{
    int z = blockIdx.y;
    const float4* src = (z == 0) ? s0 : (z == 1) ? s1 : (z == 2) ? s2 : s3;
    int i = blockIdx.x * 256 + threadIdx.x;
    if (i >= n4) return;
    float4 v = src[i];
    uint32_t h0 = pack_hi(v.x, v.y), h1 = pack_hi(v.z, v.w);
    uint32_t l0 = pack_lo(v.x, v.y, h0), l1 = pack_lo(v.z, v.w, h1);
    size_t off = (size_t)z * Ee * Ee + (size_t)i * 4;
    uint32_t* hp = (uint32_t*)(hi + off);
    uint32_t* lp = (uint32_t*)(lo + off);
    hp[0] = h0; hp[1] = h1; lp[0] = l0; lp[1] = l1;
}

// ------------------------- HMMA split-bf16 GEMM ------------------------------
// 256x128 CTA tile, 512 threads (16 warps, warp tile 64x32), K-chunk 64,
// 2-stage cp.async. z = blockIdx.z selects weight / output.
#define PCH 72
#define TA_B (256 * PCH * 2)              /* 36864: A hi or lo */
#define TW_B (128 * PCH * 2)              /* 18432: W hi or lo */
#define GSTAGE (2*TA_B + 2*TW_B)          /* 110592 */
#define GEMM_SMEM (GSTAGE * 2)            /* 221184 */

template<bool DO_COS>
__global__ __launch_bounds__(512, 1) void hmma_gemm(
    const __nv_bfloat16* __restrict__ Ahi, const __nv_bfloat16* __restrict__ Alo,
    const __nv_bfloat16* __restrict__ WhiB, const __nv_bfloat16* __restrict__ WloB,
    const float* __restrict__ theta,
    float* __restrict__ C,
    __nv_bfloat16* __restrict__ OHB, __nv_bfloat16* __restrict__ OLB)
{
    extern __shared__ __align__(16) char smem[];
    uint32_t sb = smem_u32(smem);

    int z = blockIdx.z;
    const __nv_bfloat16* Whi = WhiB + (size_t)z * Ee * Ee;
    const __nv_bfloat16* Wlo = WloB + (size_t)z * Ee * Ee;

    int tid = threadIdx.x, wid = tid >> 5, lane = tid & 31;
    int wm = wid & 3, wn = wid >> 2;          // 4 x 4 warp grid
    int g = lane >> 2, t = lane & 3;
    int lm = lane >> 3, li = lane & 7;
    int m0 = blockIdx.y * 256, n0 = blockIdx.x * 128;

    float acc[4][4][4] = {};

    auto issue = [&](int c, int bs) {
        uint32_t b0 = sb + bs * GSTAGE;
        // A: 256 rows x 8 segs = 2048 units, hi+lo
#pragma unroll
        for (int u = 0; u < 4; u++) {
            int unit = tid + u * 512;
            int row = unit >> 3, seg = unit & 7;
            size_t gA = (size_t)(m0 + row) * Ee + c * 64 + seg * 8;
            uint32_t so = (uint32_t)(row * PCH + seg * 8) * 2;
            cpa16(b0 + so,        Ahi + gA);
            cpa16(b0 + TA_B + so, Alo + gA);
        }
        // W: 128 rows x 8 segs = 1024 units, hi+lo
#pragma unroll
        for (int u = 0; u < 2; u++) {
            int unit = tid + u * 512;
            int row = unit >> 3, seg = unit & 7;
            size_t gW = (size_t)(n0 + row) * Ee + c * 64 + seg * 8;
            uint32_t so = (uint32_t)(row * PCH + seg * 8) * 2;
            cpa16(b0 + 2 * TA_B + so,        Whi + gW);
            cpa16(b0 + 2 * TA_B + TW_B + so, Wlo + gW);
        }
    };

    issue(0, 0); CPA_COMMIT();
    issue(1, 1); CPA_COMMIT();

    for (int c = 0; c < 16; c++) {
        if (c == 15) CPA_WAIT0(); else CPA_WAIT1();
        __syncthreads();

        uint32_t bufA = sb + (c & 1) * GSTAGE;
        uint32_t bufW = bufA + 2 * TA_B;

#pragma unroll
        for (int ks = 0; ks < 4; ks++) {
            uint32_t ah[4][4], al[4][4];
#pragma unroll
            for (int mf = 0; mf < 4; mf++) {
                uint32_t ad = bufA +
                    (uint32_t)(((wm * 64 + mf * 16 + (lm & 1) * 8 + li) * PCH)
                               + ks * 16 + (lm >> 1) * 8) * 2;
                ldsm_x4(ah[mf], ad);
                ldsm_x4(al[mf], ad + TA_B);
            }
#pragma unroll
            for (int nfp = 0; nfp < 2; nfp++) {
                uint32_t bd = bufW +
                    (uint32_t)(((wn * 32 + (nfp * 2 + (lm >> 1)) * 8 + li) * PCH)
                               + ks * 16 + (lm & 1) * 8) * 2;
                uint32_t bh[4], bl[4];
                ldsm_x4(bh, bd);
                ldsm_x4(bl, bd + TW_B);
#pragma unroll
                for (int mf = 0; mf < 4; mf++) {
                    mma16816(acc[mf][nfp*2],   ah[mf], bh);
                    mma16816(acc[mf][nfp*2],   ah[mf], bl);
                    mma16816(acc[mf][nfp*2],   al[mf], bh);
                    mma16816(acc[mf][nfp*2+1], ah[mf], bh + 2);
                    mma16816(acc[mf][nfp*2+1], ah[mf], bl + 2);
                    mma16816(acc[mf][nfp*2+1], al[mf], bh + 2);
                }
            }
        }
        __syncthreads();
        if (c < 14) { issue(c + 2, c & 1); CPA_COMMIT(); }
    }

    // epilogue
    __nv_bfloat16* OH = DO_COS ? OHB + (size_t)z * Mm * Ee : nullptr;
    __nv_bfloat16* OL = DO_COS ? OLB + (size_t)z * Mm * Ee : nullptr;
#pragma unroll
    for (int mf = 0; mf < 4; mf++) {
#pragma unroll
        for (int nf = 0; nf < 4; nf++) {
            int r = m0 + wm * 64 + mf * 16 + g;
            int cb = n0 + wn * 32 + nf * 8 + 2 * t;
            float v0 = acc[mf][nf][0], v1 = acc[mf][nf][1];
            float v2 = acc[mf][nf][2], v3 = acc[mf][nf][3];
            if (DO_COS) {
                float t0 = theta[cb & 63], t1 = theta[(cb + 1) & 63];
                v0 = cosf(v0 + t0); v1 = cosf(v1 + t1);
                v2 = cosf(v2 + t0); v3 = cosf(v3 + t1);
                uint32_t h0 = pack_hi(v0, v1), h1 = pack_hi(v2, v3);
                *(uint32_t*)&OH[(size_t)r * Ee + cb]       = h0;
                *(uint32_t*)&OH[(size_t)(r + 8) * Ee + cb] = h1;
                *(uint32_t*)&OL[(size_t)r * Ee + cb]       = pack_lo(v0, v1, h0);
                *(uint32_t*)&OL[(size_t)(r + 8) * Ee + cb] = pack_lo(v2, v3, h1);
            } else {
                *(float2*)&C[(size_t)r * Ee + cb]       = float2{v0, v1};
                *(float2*)&C[(size_t)(r + 8) * Ee + cb] = float2{v2, v3};
            }
        }
    }
}

// ------------------------- HMMA flash attention (unchanged from R6) ----------
#define PKV 72
#define KVB (128 * PKV * 2)              /* 18432 */
#define STAGEB (KVB * 4)                 /* 73728 */
#define ATT_SMEM (STAGEB * 3)            /* 221184 */

__global__ __launch_bounds__(256, 1) void attn_mma(
    const __nv_bfloat16* __restrict__ qhi,
    const __nv_bfloat16* __restrict__ khi, const __nv_bfloat16* __restrict__ klo,
    const __nv_bfloat16* __restrict__ vhi, const __nv_bfloat16* __restrict__ vlo,
    __nv_bfloat16* __restrict__ chi, __nv_bfloat16* __restrict__ clo)
{
    extern __shared__ __align__(16) char smem[];
    uint32_t sb = smem_u32(smem);

    int tid = threadIdx.x, wid = tid >> 5, lane = tid & 31;
    int g = lane >> 2, t = lane & 3;
    int lm = lane >> 3, li = lane & 7;
    int bh_ = blockIdx.y;
    int b = bh_ >> 4, h = bh_ & 15;
    int q0 = blockIdx.x * 128;
    size_t base = (size_t)b * Ss * Ee + (size_t)h * Dk;

    uint32_t qh[4][4];
    {
        size_t r0 = base + (size_t)(q0 + wid * 16 + g) * Ee;
        size_t r1 = r0 + 8 * (size_t)Ee;
#pragma unroll
        for (int ks = 0; ks < 4; ks++) {
            int c0 = ks * 16 + 2 * t;
            qh[ks][0] = *(const uint32_t*)&qhi[r0 + c0];
            qh[ks][1] = *(const uint32_t*)&qhi[r1 + c0];
            qh[ks][2] = *(const uint32_t*)&qhi[r0 + c0 + 8];
            qh[ks][3] = *(const uint32_t*)&qhi[r1 + c0 + 8];
        }
    }

    auto issue = [&](int j0, int s) {
        uint32_t b0 = sb + s * STAGEB;
#pragma unroll
        for (int u = 0; u < 4; u++) {
            int unit = tid + u * 256;
            int row = unit >> 3, seg = unit & 7;
            size_t gk = base + (size_t)(j0 + row) * Ee + seg * 8;
            uint32_t so = (uint32_t)(row * PKV + seg * 8) * 2;
            cpa16(b0 + so,           khi + gk);
            cpa16(b0 + KVB + so,     klo + gk);
            cpa16(b0 + 2 * KVB + so, vhi + gk);
            cpa16(b0 + 3 * KVB + so, vlo + gk);
        }
    };

    float m0 = -1e30f, m1 = -1e30f, l0 = 0.0f, l1 = 0.0f;
    float out[8][4] = {};

    issue(0, 0);   CPA_COMMIT();
    issue(128, 1); CPA_COMMIT();

    for (int tile = 0; tile < 16; tile++) {
        if (tile == 15) CPA_WAIT0(); else CPA_WAIT1();
        __syncthreads();
        if (tile < 14) { issue((tile + 2) * 128, (tile + 2) % 3); CPA_COMMIT(); }

        uint32_t kb = sb + (tile % 3) * STAGEB;
        uint32_t vb = kb + 2 * KVB;

        float s[16][4] = {};
#pragma unroll
        for (int ks = 0; ks < 4; ks++) {
#pragma unroll
            for (int nfp = 0; nfp < 8; nfp++) {
                uint32_t ad = kb +
                    (uint32_t)(((nfp * 2 + (lm >> 1)) * 8 + li) * PKV
                               + ks * 16 + (lm & 1) * 8) * 2;
                uint32_t bhv[4], blv[4];
                ldsm_x4(bhv, ad);
                ldsm_x4(blv, ad + KVB);
                mma16816(s[nfp*2],   qh[ks], bhv);
                mma16816(s[nfp*2],   qh[ks], blv);
                mma16816(s[nfp*2+1], qh[ks], bhv + 2);
                mma16816(s[nfp*2+1], qh[ks], blv + 2);
            }
        }

        float mx0 = -1e30f, mx1 = -1e30f;
#pragma unroll
        for (int nf = 0; nf < 16; nf++) {
            mx0 = fmaxf(mx0, fmaxf(s[nf][0], s[nf][1]));
            mx1 = fmaxf(mx1, fmaxf(s[nf][2], s[nf][3]));
        }
        mx0 = fmaxf(mx0, __shfl_xor_sync(0xffffffffu, mx0, 1));
        mx0 = fmaxf(mx0, __shfl_xor_sync(0xffffffffu, mx0, 2));
        mx1 = fmaxf(mx1, __shfl_xor_sync(0xffffffffu, mx1, 1));
        mx1 = fmaxf(mx1, __shfl_xor_sync(0xffffffffu, mx1, 2));
        float mn0 = fmaxf(m0, mx0), mn1 = fmaxf(m1, mx1);
        float sc0 = __expf(0.125f * (m0 - mn0));
        float sc1 = __expf(0.125f * (m1 - mn1));
#pragma unroll
        for (int nf = 0; nf < 16; nf++) {
            s[nf][0] = __expf(0.125f * (s[nf][0] - mn0));
            s[nf][1] = __expf(0.125f * (s[nf][1] - mn0));
            s[nf][2] = __expf(0.125f * (s[nf][2] - mn1));
            s[nf][3] = __expf(0.125f * (s[nf][3] - mn1));
        }

        uint32_t pa[8][4];
        float sum0 = 0.0f, sum1 = 0.0f;
#pragma unroll
        for (int k2 = 0; k2 < 8; k2++) {
            pa[k2][0] = pack_hi(s[2*k2][0],   s[2*k2][1]);
            pa[k2][1] = pack_hi(s[2*k2][2],   s[2*k2][3]);
            pa[k2][2] = pack_hi(s[2*k2+1][0], s[2*k2+1][1]);
            pa[k2][3] = pack_hi(s[2*k2+1][2], s[2*k2+1][3]);
            sum0 += unp_lo(pa[k2][0]) + unp_hi(pa[k2][0])
                  + unp_lo(pa[k2][2]) + unp_hi(pa[k2][2]);
            sum1 += unp_lo(pa[k2][1]) + unp_hi(pa[k2][1])
                  + unp_lo(pa[k2][3]) + unp_hi(pa[k2][3]);
        }
        sum0 += __shfl_xor_sync(0xffffffffu, sum0, 1);
        sum0 += __shfl_xor_sync(0xffffffffu, sum0, 2);
        sum1 += __shfl_xor_sync(0xffffffffu, sum1, 1);
        sum1 += __shfl_xor_sync(0xffffffffu, sum1, 2);
        l0 = l0 * sc0 + sum0;
        l1 = l1 * sc1 + sum1;
        m0 = mn0; m1 = mn1;
#pragma unroll
        for (int nfo = 0; nfo < 8; nfo++) {
            out[nfo][0] *= sc0; out[nfo][1] *= sc0;
            out[nfo][2] *= sc1; out[nfo][3] *= sc1;
        }

#pragma unroll
        for (int ks2 = 0; ks2 < 8; ks2++) {
#pragma unroll
            for (int nfp = 0; nfp < 4; nfp++) {
                uint32_t ad = vb +
                    (uint32_t)((ks2 * 16 + (lm & 1) * 8 + li) * PKV
                               + (nfp * 2 + (lm >> 1)) * 8) * 2;
                uint32_t bvh[4], bvl[4];
                ldsm_x4_t(bvh, ad);
                ldsm_x4_t(bvl, ad + KVB);
                mma16816(out[nfp*2],   pa[ks2], bvh);
                mma16816(out[nfp*2],   pa[ks2], bvl);
                mma16816(out[nfp*2+1], pa[ks2], bvh + 2);
                mma16816(out[nfp*2+1], pa[ks2], bvl + 2);
            }
        }
    }

    float inv0 = 1.0f / l0, inv1 = 1.0f / l1;
    size_t r0 = base + (size_t)(q0 + wid * 16 + g) * Ee;
    size_t r1 = r0 + 8 * (size_t)Ee;
#pragma unroll
    for (int nfo = 0; nfo < 8; nfo++) {
        int d = nfo * 8 + 2 * t;
        float v0 = out[nfo][0] * inv0, v1 = out[nfo][1] * inv0;
        float v2 = out[nfo][2] * inv1, v3 = out[nfo][3] * inv1;
        uint32_t h0 = pack_hi(v0, v1), h1 = pack_hi(v2, v3);
        *(uint32_t*)&chi[r0 + d] = h0;
        *(uint32_t*)&chi[r1 + d] = h1;
        *(uint32_t*)&clo[r0 + d] = pack_lo(v0, v1, h0);
        *(uint32_t*)&clo[r1 + d] = pack_lo(v2, v3, h1);
    }
}

// ---------------------------------------------------------------------------
extern "C" void kernel_launch(void* const* d_in, const int* in_sizes, int n_in,
                              void* d_out, int out_size)
{
    const float* x     = (const float*)d_in[0];
    const float* Wq    = (const float*)d_in[1];
    const float* Wk    = (const float*)d_in[2];
    const float* Wv    = (const float*)d_in[3];
    const float* Wo    = (const float*)d_in[4];
    const float* theta = (const float*)d_in[5];
    float* out = (float*)d_out;

    __nv_bfloat16 *xhi, *xlo, *qkvhi, *qkvlo, *chi, *clo, *whi, *wlo;
    cudaGetSymbolAddress((void**)&xhi, g_xhi);
    cudaGetSymbolAddress((void**)&xlo, g_xlo);
    cudaGetSymbolAddress((void**)&qkvhi, g_qkvhi);
    cudaGetSymbolAddress((void**)&qkvlo, g_qkvlo);
    cudaGetSymbolAddress((void**)&chi, g_chi);
    cudaGetSymbolAddress((void**)&clo, g_clo);
    cudaGetSymbolAddress((void**)&whi, g_whi);
    cudaGetSymbolAddress((void**)&wlo, g_wlo);

    cudaFuncSetAttribute(hmma_gemm<true>,
        cudaFuncAttributeMaxDynamicSharedMemorySize, GEMM_SMEM);
    cudaFuncSetAttribute(hmma_gemm<false>,
        cudaFuncAttributeMaxDynamicSharedMemorySize, GEMM_SMEM);
    cudaFuncSetAttribute(attn_mma,
        cudaFuncAttributeMaxDynamicSharedMemorySize, ATT_SMEM);

    int n4x = Mm * Ee / 4;
    int n4w = Ee * Ee / 4;
    split_kernel<<<(n4x + 255) / 256, 256>>>((const float4*)x, xhi, xlo, n4x);
    dim3 gw((n4w + 255) / 256, 4);
    split4_kernel<<<gw, 256>>>((const float4*)Wq, (const float4*)Wk,
                               (const float4*)Wv, (const float4*)Wo,
                               whi, wlo, n4w);

    dim3 g1(Ee / 128, Mm / 256, 3);   // fused Q/K/V projections, 256-row tiles
    hmma_gemm<true><<<g1, 512, GEMM_SMEM>>>(xhi, xlo, whi, wlo, theta,
                                            nullptr, qkvhi, qkvlo);

    size_t off = (size_t)Mm * Ee;
    dim3 g2(Ss / 128, Bb * Hh);       // (16, 64)
    attn_mma<<<g2, 256, ATT_SMEM>>>(qkvhi,
                                    qkvhi + off, qkvlo + off,
                                    qkvhi + 2*off, qkvlo + 2*off,
                                    chi, clo);

    dim3 g3(Ee / 128, Mm / 256, 1);
    hmma_gemm<false><<<g3, 512, GEMM_SMEM>>>(chi, clo,
        whi + 3*(size_t)Ee*Ee, wlo + 3*(size_t)Ee*Ee, nullptr, out,
        nullptr, nullptr);
}